// round 1
// baseline (speedup 1.0000x reference)
#include <cuda_runtime.h>
#include <math.h>

// ---------------- problem constants ----------------
#define SV 2048
#define SA 512
#define S_TOT 2560
#define D_MODEL 1024
#define NH 16
#define DH 64
#define FF 4096
#define NL 2

// ---------------- scratch (device globals; no allocation) ----------------
__device__ float g_x[S_TOT * D_MODEL];
__device__ float g_a[S_TOT * D_MODEL];
__device__ float g_q[S_TOT * D_MODEL];
__device__ float g_k[S_TOT * D_MODEL];
__device__ float g_v[S_TOT * D_MODEL];
__device__ float g_o[S_TOT * D_MODEL];
__device__ float g_h[S_TOT * FF];
__device__ float g_m6[2 * 6 * D_MODEL];

// ---------------- block reduce (sum of two values) ----------------
__device__ __forceinline__ void blockReduce2(float& s, float& ss) {
    __shared__ float bufs[8], bufss[8];
    #pragma unroll
    for (int o = 16; o; o >>= 1) {
        s  += __shfl_xor_sync(0xffffffffu, s,  o);
        ss += __shfl_xor_sync(0xffffffffu, ss, o);
    }
    int w = threadIdx.x >> 5;
    if ((threadIdx.x & 31) == 0) { bufs[w] = s; bufss[w] = ss; }
    __syncthreads();
    if (threadIdx.x < 32) {
        s  = (threadIdx.x < 8) ? bufs[threadIdx.x]  : 0.f;
        ss = (threadIdx.x < 8) ? bufss[threadIdx.x] : 0.f;
        #pragma unroll
        for (int o = 4; o; o >>= 1) {
            s  += __shfl_xor_sync(0xffffffffu, s,  o);
            ss += __shfl_xor_sync(0xffffffffu, ss, o);
        }
        if (threadIdx.x == 0) { bufs[0] = s; bufss[0] = ss; }
    }
    __syncthreads();
    s = bufs[0]; ss = bufss[0];
}

// ---------------- m6 = mod[e,l] + t_mod[e] ----------------
__global__ void m6_kernel(const float* __restrict__ mod, const float* __restrict__ vt,
                          const float* __restrict__ at, float* __restrict__ m6, int l) {
    int idx = blockIdx.x * blockDim.x + threadIdx.x;
    if (idx >= 2 * 6 * D_MODEL) return;
    int e = idx / (6 * D_MODEL);
    int rem = idx % (6 * D_MODEL); // j*D + d
    m6[idx] = mod[((size_t)(e * NL + l) * 6) * D_MODEL + rem] + (e ? at[rem] : vt[rem]);
}

// ---------------- a = LN(x) * (1+sc) + sh  (per-row, 256 thr, D=1024) ----------------
__global__ void __launch_bounds__(256) lnmod_kernel(const float* __restrict__ x, float* __restrict__ a,
                                                    const float* __restrict__ m6, int jsh, int jsc) {
    int row = blockIdx.x;
    int e = (row >= SV) ? 1 : 0;
    const float4* shv4 = (const float4*)(m6 + (size_t)(e * 6 + jsh) * D_MODEL);
    const float4* scv4 = (const float4*)(m6 + (size_t)(e * 6 + jsc) * D_MODEL);
    float4 v = ((const float4*)(x + (size_t)row * D_MODEL))[threadIdx.x];
    float s  = v.x + v.y + v.z + v.w;
    float ss = v.x * v.x + v.y * v.y + v.z * v.z + v.w * v.w;
    blockReduce2(s, ss);
    float mu  = s * (1.f / D_MODEL);
    float var = ss * (1.f / D_MODEL) - mu * mu;
    float r = rsqrtf(var + 1e-6f);
    float4 sh = shv4[threadIdx.x];
    float4 sc = scv4[threadIdx.x];
    float4 o;
    o.x = (v.x - mu) * r * (1.f + sc.x) + sh.x;
    o.y = (v.y - mu) * r * (1.f + sc.y) + sh.y;
    o.z = (v.z - mu) * r * (1.f + sc.z) + sh.z;
    o.w = (v.w - mu) * r * (1.f + sc.w) + sh.w;
    ((float4*)(a + (size_t)row * D_MODEL))[threadIdx.x] = o;
}

// ---------------- RMSNorm(g) + RoPE, in place on q/k ----------------
__global__ void __launch_bounds__(256) rmsrope_kernel(float* __restrict__ q, const float* __restrict__ gbase,
                                                      const float* __restrict__ vfreq, const float* __restrict__ afreq,
                                                      int l) {
    int row = blockIdx.x;
    int e = (row >= SV) ? 1 : 0;
    int pos = e ? row - SV : row;
    const float* fr = e ? (afreq + (size_t)pos * (DH / 2)) : (vfreq + (size_t)pos * (DH / 2));
    const float* g = gbase + (size_t)(e * NL + l) * D_MODEL;
    float4 v = ((const float4*)(q + (size_t)row * D_MODEL))[threadIdx.x];
    float ss = v.x * v.x + v.y * v.y + v.z * v.z + v.w * v.w;
    float dummy = 0.f;
    blockReduce2(ss, dummy);
    float r = rsqrtf(ss * (1.f / D_MODEL) + 1e-6f);
    float4 gv = ((const float4*)g)[threadIdx.x];
    int d0 = threadIdx.x * 4;
    int j0 = (d0 & (DH - 1)) >> 1;
    int j1 = j0 + 1;
    float th0 = fr[j0], th1 = fr[j1];
    float c0 = cosf(th0), s0 = sinf(th0);
    float c1 = cosf(th1), s1 = sinf(th1);
    float xe0 = v.x * r * gv.x, xo0 = v.y * r * gv.y;
    float xe1 = v.z * r * gv.z, xo1 = v.w * r * gv.w;
    float4 o;
    o.x = xe0 * c0 - xo0 * s0;
    o.y = xe0 * s0 + xo0 * c0;
    o.z = xe1 * c1 - xo1 * s1;
    o.w = xe1 * s1 + xo1 * c1;
    ((float4*)(q + (size_t)row * D_MODEL))[threadIdx.x] = o;
}

// ---------------- SGEMM: C = epi(A @ B + bias)  (M%128==0, N%128==0, K%8==0) ----------------
// EPI 0: bias   EPI 1: gelu(tanh)   EPI 2: C = res + gate * (acc + bias)
template <int EPI>
__global__ void __launch_bounds__(256) sgemm_kernel(
    const float* __restrict__ A, const float* __restrict__ B,
    const float* __restrict__ bias, float* __restrict__ C,
    const float* __restrict__ res, const float* __restrict__ gate,
    int M, int N, int K) {
    __shared__ float As[8][128];
    __shared__ float Bs[8][128];
    int tid = threadIdx.x;
    const float* Ab = A + (size_t)blockIdx.y * 128 * K;
    const float* Bb = B + (size_t)blockIdx.x * 128;
    int ar = (tid * 4) >> 3, ac = (tid * 4) & 7;
    int br = (tid * 4) >> 7, bc = (tid * 4) & 127;
    int ty = tid >> 4, tx = tid & 15;
    float acc[8][8];
    #pragma unroll
    for (int i = 0; i < 8; i++)
        #pragma unroll
        for (int j = 0; j < 8; j++) acc[i][j] = 0.f;

    for (int kb = 0; kb < K; kb += 8) {
        float4 av = *(const float4*)(Ab + (size_t)ar * K + kb + ac);
        float4 bv = *(const float4*)(Bb + (size_t)(kb + br) * N + bc);
        __syncthreads();
        As[ac + 0][ar] = av.x; As[ac + 1][ar] = av.y;
        As[ac + 2][ar] = av.z; As[ac + 3][ar] = av.w;
        *(float4*)&Bs[br][bc] = bv;
        __syncthreads();
        #pragma unroll
        for (int k = 0; k < 8; k++) {
            float4 a0 = *(float4*)&As[k][ty * 8];
            float4 a1 = *(float4*)&As[k][ty * 8 + 4];
            float4 b0 = *(float4*)&Bs[k][tx * 8];
            float4 b1 = *(float4*)&Bs[k][tx * 8 + 4];
            float ra[8] = {a0.x, a0.y, a0.z, a0.w, a1.x, a1.y, a1.z, a1.w};
            float rb[8] = {b0.x, b0.y, b0.z, b0.w, b1.x, b1.y, b1.z, b1.w};
            #pragma unroll
            for (int i = 0; i < 8; i++)
                #pragma unroll
                for (int j = 0; j < 8; j++) acc[i][j] += ra[i] * rb[j];
        }
    }

    int row0 = blockIdx.y * 128 + ty * 8;
    int col0 = blockIdx.x * 128 + tx * 8;
    #pragma unroll
    for (int i = 0; i < 8; i++) {
        int row = row0 + i;
        #pragma unroll
        for (int j = 0; j < 8; j++) {
            int col = col0 + j;
            float v = acc[i][j] + bias[col];
            if (EPI == 1) {
                float t = v;
                v = 0.5f * t * (1.f + tanhf(0.7978845608028654f * (t + 0.044715f * t * t * t)));
            }
            if (EPI == 2) {
                v = res[(size_t)row * N + col] + gate[col] * v;
            }
            C[(size_t)row * N + col] = v;
        }
    }
}

// ---------------- flash attention, structural mask ----------------
// grid: (NH, S_TOT/64), 256 threads. Per thread: 1 query row quad-split, 16 cols.
__global__ void __launch_bounds__(256) attn_kernel(const float* __restrict__ Q,
                                                   const float* __restrict__ K,
                                                   const float* __restrict__ V,
                                                   float* __restrict__ O) {
    extern __shared__ float sm[];
    float* Qs = sm;                 // 64*65
    float* Ks = sm + 64 * 65;       // 64*65
    float* Vs = sm + 2 * 64 * 65;   // 64*65
    float* Ps = sm + 3 * 64 * 65;   // 64*64
    int h = blockIdx.x, qt = blockIdx.y;
    int q0 = qt * 64;
    int tid = threadIdx.x;
    int qr = tid >> 2, sub = tid & 3;
    int cb = sub * 16, db = sub * 16;

    for (int i = tid; i < 4096; i += 256) {
        int r = i >> 6, c = i & 63;
        Qs[r * 65 + c] = Q[(size_t)(q0 + r) * D_MODEL + h * DH + c];
    }

    float m = -1e30f, lsum = 0.f;
    float o[16];
    #pragma unroll
    for (int i = 0; i < 16; i++) o[i] = 0.f;

    int kend = (q0 < SV) ? SV : (q0 + 64);
    for (int kb = 0; kb < kend; kb += 64) {
        __syncthreads();
        for (int i = tid; i < 4096; i += 256) {
            int r = i >> 6, c = i & 63;
            Ks[r * 65 + c] = K[(size_t)(kb + r) * D_MODEL + h * DH + c];
            Vs[r * 65 + c] = V[(size_t)(kb + r) * D_MODEL + h * DH + c];
        }
        __syncthreads();

        float s[16];
        #pragma unroll
        for (int cc = 0; cc < 16; cc++) s[cc] = 0.f;
        for (int k0 = 0; k0 < 64; k0 += 16) {
            float qv[16];
            #pragma unroll
            for (int k = 0; k < 16; k++) qv[k] = Qs[qr * 65 + k0 + k];
            #pragma unroll
            for (int cc = 0; cc < 16; cc++) {
                const float* kr = &Ks[(cb + cc) * 65 + k0];
                #pragma unroll
                for (int k = 0; k < 16; k++) s[cc] += qv[k] * kr[k];
            }
        }
        #pragma unroll
        for (int cc = 0; cc < 16; cc++) s[cc] *= 0.125f;
        if (kb >= SV) {
            #pragma unroll
            for (int cc = 0; cc < 16; cc++)
                if (kb + cb + cc > q0 + qr) s[cc] = -1e9f;
        }
        float tmax = -1e30f;
        #pragma unroll
        for (int cc = 0; cc < 16; cc++) tmax = fmaxf(tmax, s[cc]);
        tmax = fmaxf(tmax, __shfl_xor_sync(0xffffffffu, tmax, 1));
        tmax = fmaxf(tmax, __shfl_xor_sync(0xffffffffu, tmax, 2));
        float mn = fmaxf(m, tmax);
        float corr = expf(m - mn);
        float psum = 0.f;
        #pragma unroll
        for (int cc = 0; cc < 16; cc++) {
            float p = expf(s[cc] - mn);
            psum += p;
            Ps[qr * 64 + cb + cc] = p;
        }
        psum += __shfl_xor_sync(0xffffffffu, psum, 1);
        psum += __shfl_xor_sync(0xffffffffu, psum, 2);
        lsum = lsum * corr + psum;
        m = mn;
        #pragma unroll
        for (int dd = 0; dd < 16; dd++) o[dd] *= corr;
        __syncwarp();
        for (int c = 0; c < 64; c++) {
            float p = Ps[qr * 64 + c];
            const float* vr = &Vs[c * 65 + db];
            #pragma unroll
            for (int dd = 0; dd < 16; dd++) o[dd] += p * vr[dd];
        }
    }
    float inv = 1.f / lsum;
    #pragma unroll
    for (int dd = 0; dd < 16; dd++)
        O[(size_t)(q0 + qr) * D_MODEL + h * DH + db + dd] = o[dd] * inv;
}

// ---------------- host ----------------
extern "C" void kernel_launch(void* const* d_in, const int* in_sizes, int n_in,
                              void* d_out, int out_size) {
    const float* video  = (const float*)d_in[0];
    const float* action = (const float*)d_in[1];
    const float* vfreq  = (const float*)d_in[2];
    const float* afreq  = (const float*)d_in[3];
    const float* vtmod  = (const float*)d_in[4];
    const float* atmod  = (const float*)d_in[5];
    const float* Wq = (const float*)d_in[6];
    const float* Wk = (const float*)d_in[7];
    const float* Wv = (const float*)d_in[8];
    const float* Wo = (const float*)d_in[9];
    const float* bq = (const float*)d_in[10];
    const float* bk = (const float*)d_in[11];
    const float* bv = (const float*)d_in[12];
    const float* bo = (const float*)d_in[13];
    const float* gq = (const float*)d_in[14];
    const float* gk = (const float*)d_in[15];
    const float* mod = (const float*)d_in[16];
    const float* W1 = (const float*)d_in[17];
    const float* b1 = (const float*)d_in[18];
    const float* W2 = (const float*)d_in[19];
    const float* b2 = (const float*)d_in[20];
    float* out = (float*)d_out;

    float *x, *a, *q, *k, *v, *o, *hbuf, *m6;
    cudaGetSymbolAddress((void**)&x, g_x);
    cudaGetSymbolAddress((void**)&a, g_a);
    cudaGetSymbolAddress((void**)&q, g_q);
    cudaGetSymbolAddress((void**)&k, g_k);
    cudaGetSymbolAddress((void**)&v, g_v);
    cudaGetSymbolAddress((void**)&o, g_o);
    cudaGetSymbolAddress((void**)&hbuf, g_h);
    cudaGetSymbolAddress((void**)&m6, g_m6);

    const int SMEM_ATTN = (3 * 64 * 65 + 64 * 64) * 4;
    cudaFuncSetAttribute(attn_kernel, cudaFuncAttributeMaxDynamicSharedMemorySize, SMEM_ATTN);

    cudaMemcpyAsync(x, video, (size_t)SV * D_MODEL * sizeof(float), cudaMemcpyDeviceToDevice);
    cudaMemcpyAsync(x + (size_t)SV * D_MODEL, action, (size_t)SA * D_MODEL * sizeof(float),
                    cudaMemcpyDeviceToDevice);

    for (int l = 0; l < NL; l++) {
        m6_kernel<<<(2 * 6 * D_MODEL + 255) / 256, 256>>>(mod, vtmod, atmod, m6, l);
        lnmod_kernel<<<S_TOT, 256>>>(x, a, m6, 0, 1);

        for (int e = 0; e < 2; e++) {
            int M = e ? SA : SV;
            size_t roff = e ? (size_t)SV * D_MODEL : 0;
            size_t woff = (size_t)(e * NL + l) * D_MODEL * D_MODEL;
            size_t boff = (size_t)(e * NL + l) * D_MODEL;
            dim3 g(D_MODEL / 128, M / 128);
            sgemm_kernel<0><<<g, 256>>>(a + roff, Wq + woff, bq + boff, q + roff, nullptr, nullptr, M, D_MODEL, D_MODEL);
            sgemm_kernel<0><<<g, 256>>>(a + roff, Wk + woff, bk + boff, k + roff, nullptr, nullptr, M, D_MODEL, D_MODEL);
            sgemm_kernel<0><<<g, 256>>>(a + roff, Wv + woff, bv + boff, v + roff, nullptr, nullptr, M, D_MODEL, D_MODEL);
        }
        rmsrope_kernel<<<S_TOT, 256>>>(q, gq, vfreq, afreq, l);
        rmsrope_kernel<<<S_TOT, 256>>>(k, gk, vfreq, afreq, l);

        attn_kernel<<<dim3(NH, S_TOT / 64), 256, SMEM_ATTN>>>(q, k, v, o);

        for (int e = 0; e < 2; e++) {
            int M = e ? SA : SV;
            size_t roff = e ? (size_t)SV * D_MODEL : 0;
            size_t woff = (size_t)(e * NL + l) * D_MODEL * D_MODEL;
            size_t boff = (size_t)(e * NL + l) * D_MODEL;
            dim3 g(D_MODEL / 128, M / 128);
            sgemm_kernel<2><<<g, 256>>>(o + roff, Wo + woff, bo + boff, x + roff,
                                        x + roff, m6 + (size_t)(e * 6 + 2) * D_MODEL, M, D_MODEL, D_MODEL);
        }

        lnmod_kernel<<<S_TOT, 256>>>(x, a, m6, 3, 4);

        for (int e = 0; e < 2; e++) {
            int M = e ? SA : SV;
            size_t roff = e ? (size_t)SV * D_MODEL : 0;
            size_t hoff = e ? (size_t)SV * FF : 0;
            size_t w1off = (size_t)(e * NL + l) * D_MODEL * FF;
            size_t b1off = (size_t)(e * NL + l) * FF;
            size_t w2off = (size_t)(e * NL + l) * FF * D_MODEL;
            size_t b2off = (size_t)(e * NL + l) * D_MODEL;
            dim3 g1(FF / 128, M / 128);
            sgemm_kernel<1><<<g1, 256>>>(a + roff, W1 + w1off, b1 + b1off, hbuf + hoff,
                                         nullptr, nullptr, M, FF, D_MODEL);
            dim3 g2(D_MODEL / 128, M / 128);
            sgemm_kernel<2><<<g2, 256>>>(hbuf + hoff, W2 + w2off, b2 + b2off, x + roff,
                                         x + roff, m6 + (size_t)(e * 6 + 5) * D_MODEL, M, D_MODEL, FF);
        }
    }

    cudaMemcpyAsync(out, x, (size_t)S_TOT * D_MODEL * sizeof(float), cudaMemcpyDeviceToDevice);
}

// round 2
// speedup vs baseline: 1.0052x; 1.0052x over previous
#include <cuda_runtime.h>
#include <math.h>

// ---------------- problem constants ----------------
#define SV 2048
#define SA 512
#define S_TOT 2560
#define D_MODEL 1024
#define NH 16
#define DH 64
#define FF 4096
#define NL 2

// ---------------- scratch (device globals; no allocation) ----------------
__device__ float g_x[S_TOT * D_MODEL];
__device__ float g_a[S_TOT * D_MODEL];
__device__ float g_q[S_TOT * D_MODEL];
__device__ float g_k[S_TOT * D_MODEL];
__device__ float g_v[S_TOT * D_MODEL];
__device__ float g_o[S_TOT * D_MODEL];
__device__ float g_h[S_TOT * FF];
__device__ float g_m6[2 * 6 * D_MODEL];

// ---------------- block reduce (sum of two values) ----------------
__device__ __forceinline__ void blockReduce2(float& s, float& ss) {
    __shared__ float bufs[8], bufss[8];
    #pragma unroll
    for (int o = 16; o; o >>= 1) {
        s  += __shfl_xor_sync(0xffffffffu, s,  o);
        ss += __shfl_xor_sync(0xffffffffu, ss, o);
    }
    int w = threadIdx.x >> 5;
    if ((threadIdx.x & 31) == 0) { bufs[w] = s; bufss[w] = ss; }
    __syncthreads();
    if (threadIdx.x < 32) {
        s  = (threadIdx.x < 8) ? bufs[threadIdx.x]  : 0.f;
        ss = (threadIdx.x < 8) ? bufss[threadIdx.x] : 0.f;
        #pragma unroll
        for (int o = 4; o; o >>= 1) {
            s  += __shfl_xor_sync(0xffffffffu, s,  o);
            ss += __shfl_xor_sync(0xffffffffu, ss, o);
        }
        if (threadIdx.x == 0) { bufs[0] = s; bufss[0] = ss; }
    }
    __syncthreads();
    s = bufs[0]; ss = bufss[0];
}

// ---------------- m6 = mod[e,l] + t_mod[e] ----------------
__global__ void m6_kernel(const float* __restrict__ mod, const float* __restrict__ vt,
                          const float* __restrict__ at, float* __restrict__ m6, int l) {
    int idx = blockIdx.x * blockDim.x + threadIdx.x;
    if (idx >= 2 * 6 * D_MODEL) return;
    int e = idx / (6 * D_MODEL);
    int rem = idx % (6 * D_MODEL); // j*D + d
    m6[idx] = mod[((size_t)(e * NL + l) * 6) * D_MODEL + rem] + (e ? at[rem] : vt[rem]);
}

// ---------------- a = LN(x) * (1+sc) + sh  (per-row, 256 thr, D=1024) ----------------
__global__ void __launch_bounds__(256) lnmod_kernel(const float* __restrict__ x, float* __restrict__ a,
                                                    const float* __restrict__ m6, int jsh, int jsc) {
    int row = blockIdx.x;
    int e = (row >= SV) ? 1 : 0;
    const float4* shv4 = (const float4*)(m6 + (size_t)(e * 6 + jsh) * D_MODEL);
    const float4* scv4 = (const float4*)(m6 + (size_t)(e * 6 + jsc) * D_MODEL);
    float4 v = ((const float4*)(x + (size_t)row * D_MODEL))[threadIdx.x];
    float s  = v.x + v.y + v.z + v.w;
    float ss = v.x * v.x + v.y * v.y + v.z * v.z + v.w * v.w;
    blockReduce2(s, ss);
    float mu  = s * (1.f / D_MODEL);
    float var = ss * (1.f / D_MODEL) - mu * mu;
    float r = rsqrtf(var + 1e-6f);
    float4 sh = shv4[threadIdx.x];
    float4 sc = scv4[threadIdx.x];
    float4 o;
    o.x = (v.x - mu) * r * (1.f + sc.x) + sh.x;
    o.y = (v.y - mu) * r * (1.f + sc.y) + sh.y;
    o.z = (v.z - mu) * r * (1.f + sc.z) + sh.z;
    o.w = (v.w - mu) * r * (1.f + sc.w) + sh.w;
    ((float4*)(a + (size_t)row * D_MODEL))[threadIdx.x] = o;
}

// ---------------- RMSNorm(g) + RoPE, in place on q/k ----------------
__global__ void __launch_bounds__(256) rmsrope_kernel(float* __restrict__ q, const float* __restrict__ gbase,
                                                      const float* __restrict__ vfreq, const float* __restrict__ afreq,
                                                      int l) {
    int row = blockIdx.x;
    int e = (row >= SV) ? 1 : 0;
    int pos = e ? row - SV : row;
    const float* fr = e ? (afreq + (size_t)pos * (DH / 2)) : (vfreq + (size_t)pos * (DH / 2));
    const float* g = gbase + (size_t)(e * NL + l) * D_MODEL;
    float4 v = ((const float4*)(q + (size_t)row * D_MODEL))[threadIdx.x];
    float ss = v.x * v.x + v.y * v.y + v.z * v.z + v.w * v.w;
    float dummy = 0.f;
    blockReduce2(ss, dummy);
    float r = rsqrtf(ss * (1.f / D_MODEL) + 1e-6f);
    float4 gv = ((const float4*)g)[threadIdx.x];
    int d0 = threadIdx.x * 4;
    int j0 = (d0 & (DH - 1)) >> 1;
    int j1 = j0 + 1;
    float th0 = fr[j0], th1 = fr[j1];
    float c0 = cosf(th0), s0 = sinf(th0);
    float c1 = cosf(th1), s1 = sinf(th1);
    float xe0 = v.x * r * gv.x, xo0 = v.y * r * gv.y;
    float xe1 = v.z * r * gv.z, xo1 = v.w * r * gv.w;
    float4 o;
    o.x = xe0 * c0 - xo0 * s0;
    o.y = xe0 * s0 + xo0 * c0;
    o.z = xe1 * c1 - xo1 * s1;
    o.w = xe1 * s1 + xo1 * c1;
    ((float4*)(q + (size_t)row * D_MODEL))[threadIdx.x] = o;
}

// ---------------- SGEMM: C = epi(A @ B + bias)  (M%128==0, N%128==0, K%8==0) ----------------
// EPI 0: bias   EPI 1: gelu(tanh)   EPI 2: C = res + gate * (acc + bias)
template <int EPI>
__global__ void __launch_bounds__(256) sgemm_kernel(
    const float* __restrict__ A, const float* __restrict__ B,
    const float* __restrict__ bias, float* __restrict__ C,
    const float* __restrict__ res, const float* __restrict__ gate,
    int M, int N, int K) {
    __shared__ float As[8][128];
    __shared__ float Bs[8][128];
    int tid = threadIdx.x;
    const float* Ab = A + (size_t)blockIdx.y * 128 * K;
    const float* Bb = B + (size_t)blockIdx.x * 128;
    int ar = (tid * 4) >> 3, ac = (tid * 4) & 7;
    int br = (tid * 4) >> 7, bc = (tid * 4) & 127;
    int ty = tid >> 4, tx = tid & 15;
    float acc[8][8];
    #pragma unroll
    for (int i = 0; i < 8; i++)
        #pragma unroll
        for (int j = 0; j < 8; j++) acc[i][j] = 0.f;

    for (int kb = 0; kb < K; kb += 8) {
        float4 av = *(const float4*)(Ab + (size_t)ar * K + kb + ac);
        float4 bv = *(const float4*)(Bb + (size_t)(kb + br) * N + bc);
        __syncthreads();
        As[ac + 0][ar] = av.x; As[ac + 1][ar] = av.y;
        As[ac + 2][ar] = av.z; As[ac + 3][ar] = av.w;
        *(float4*)&Bs[br][bc] = bv;
        __syncthreads();
        #pragma unroll
        for (int k = 0; k < 8; k++) {
            float4 a0 = *(float4*)&As[k][ty * 8];
            float4 a1 = *(float4*)&As[k][ty * 8 + 4];
            float4 b0 = *(float4*)&Bs[k][tx * 8];
            float4 b1 = *(float4*)&Bs[k][tx * 8 + 4];
            float ra[8] = {a0.x, a0.y, a0.z, a0.w, a1.x, a1.y, a1.z, a1.w};
            float rb[8] = {b0.x, b0.y, b0.z, b0.w, b1.x, b1.y, b1.z, b1.w};
            #pragma unroll
            for (int i = 0; i < 8; i++)
                #pragma unroll
                for (int j = 0; j < 8; j++) acc[i][j] += ra[i] * rb[j];
        }
    }

    int row0 = blockIdx.y * 128 + ty * 8;
    int col0 = blockIdx.x * 128 + tx * 8;
    #pragma unroll
    for (int i = 0; i < 8; i++) {
        int row = row0 + i;
        #pragma unroll
        for (int j = 0; j < 8; j++) {
            int col = col0 + j;
            float v = acc[i][j] + bias[col];
            if (EPI == 1) {
                float t = v;
                v = 0.5f * t * (1.f + tanhf(0.7978845608028654f * (t + 0.044715f * t * t * t)));
            }
            if (EPI == 2) {
                v = res[(size_t)row * N + col] + gate[col] * v;
            }
            C[(size_t)row * N + col] = v;
        }
    }
}

// ---------------- flash attention, structural mask ----------------
// grid: (NH, S_TOT/64), 256 threads. Per thread: 1 query row quad-split, 16 cols.
__global__ void __launch_bounds__(256) attn_kernel(const float* __restrict__ Q,
                                                   const float* __restrict__ K,
                                                   const float* __restrict__ V,
                                                   float* __restrict__ O) {
    extern __shared__ float sm[];
    float* Qs = sm;                 // 64*65
    float* Ks = sm + 64 * 65;       // 64*65
    float* Vs = sm + 2 * 64 * 65;   // 64*65
    float* Ps = sm + 3 * 64 * 65;   // 64*64
    int h = blockIdx.x, qt = blockIdx.y;
    int q0 = qt * 64;
    int tid = threadIdx.x;
    int qr = tid >> 2, sub = tid & 3;
    int cb = sub * 16, db = sub * 16;

    for (int i = tid; i < 4096; i += 256) {
        int r = i >> 6, c = i & 63;
        Qs[r * 65 + c] = Q[(size_t)(q0 + r) * D_MODEL + h * DH + c];
    }

    float m = -1e30f, lsum = 0.f;
    float o[16];
    #pragma unroll
    for (int i = 0; i < 16; i++) o[i] = 0.f;

    int kend = (q0 < SV) ? SV : (q0 + 64);
    for (int kb = 0; kb < kend; kb += 64) {
        __syncthreads();
        for (int i = tid; i < 4096; i += 256) {
            int r = i >> 6, c = i & 63;
            Ks[r * 65 + c] = K[(size_t)(kb + r) * D_MODEL + h * DH + c];
            Vs[r * 65 + c] = V[(size_t)(kb + r) * D_MODEL + h * DH + c];
        }
        __syncthreads();

        float s[16];
        #pragma unroll
        for (int cc = 0; cc < 16; cc++) s[cc] = 0.f;
        for (int k0 = 0; k0 < 64; k0 += 16) {
            float qv[16];
            #pragma unroll
            for (int k = 0; k < 16; k++) qv[k] = Qs[qr * 65 + k0 + k];
            #pragma unroll
            for (int cc = 0; cc < 16; cc++) {
                const float* kr = &Ks[(cb + cc) * 65 + k0];
                #pragma unroll
                for (int k = 0; k < 16; k++) s[cc] += qv[k] * kr[k];
            }
        }
        #pragma unroll
        for (int cc = 0; cc < 16; cc++) s[cc] *= 0.125f;
        if (kb >= SV) {
            #pragma unroll
            for (int cc = 0; cc < 16; cc++)
                if (kb + cb + cc > q0 + qr) s[cc] = -1e9f;
        }
        float tmax = -1e30f;
        #pragma unroll
        for (int cc = 0; cc < 16; cc++) tmax = fmaxf(tmax, s[cc]);
        tmax = fmaxf(tmax, __shfl_xor_sync(0xffffffffu, tmax, 1));
        tmax = fmaxf(tmax, __shfl_xor_sync(0xffffffffu, tmax, 2));
        float mn = fmaxf(m, tmax);
        float corr = expf(m - mn);
        float psum = 0.f;
        #pragma unroll
        for (int cc = 0; cc < 16; cc++) {
            float p = expf(s[cc] - mn);
            psum += p;
            Ps[qr * 64 + cb + cc] = p;
        }
        psum += __shfl_xor_sync(0xffffffffu, psum, 1);
        psum += __shfl_xor_sync(0xffffffffu, psum, 2);
        lsum = lsum * corr + psum;
        m = mn;
        #pragma unroll
        for (int dd = 0; dd < 16; dd++) o[dd] *= corr;
        __syncwarp();
        for (int c = 0; c < 64; c++) {
            float p = Ps[qr * 64 + c];
            const float* vr = &Vs[c * 65 + db];
            #pragma unroll
            for (int dd = 0; dd < 16; dd++) o[dd] += p * vr[dd];
        }
    }
    float inv = 1.f / lsum;
    #pragma unroll
    for (int dd = 0; dd < 16; dd++)
        O[(size_t)(q0 + qr) * D_MODEL + h * DH + db + dd] = o[dd] * inv;
}

// ---------------- host ----------------
extern "C" void kernel_launch(void* const* d_in, const int* in_sizes, int n_in,
                              void* d_out, int out_size) {
    const float* video  = (const float*)d_in[0];
    const float* action = (const float*)d_in[1];
    const float* vfreq  = (const float*)d_in[2];
    const float* afreq  = (const float*)d_in[3];
    const float* vtmod  = (const float*)d_in[4];
    const float* atmod  = (const float*)d_in[5];
    const float* Wq = (const float*)d_in[6];
    const float* Wk = (const float*)d_in[7];
    const float* Wv = (const float*)d_in[8];
    const float* Wo = (const float*)d_in[9];
    const float* bq = (const float*)d_in[10];
    const float* bk = (const float*)d_in[11];
    const float* bv = (const float*)d_in[12];
    const float* bo = (const float*)d_in[13];
    const float* gq = (const float*)d_in[14];
    const float* gk = (const float*)d_in[15];
    const float* mod = (const float*)d_in[16];
    const float* W1 = (const float*)d_in[17];
    const float* b1 = (const float*)d_in[18];
    const float* W2 = (const float*)d_in[19];
    const float* b2 = (const float*)d_in[20];
    float* out = (float*)d_out;

    float *x, *a, *q, *k, *v, *o, *hbuf, *m6;
    cudaGetSymbolAddress((void**)&x, g_x);
    cudaGetSymbolAddress((void**)&a, g_a);
    cudaGetSymbolAddress((void**)&q, g_q);
    cudaGetSymbolAddress((void**)&k, g_k);
    cudaGetSymbolAddress((void**)&v, g_v);
    cudaGetSymbolAddress((void**)&o, g_o);
    cudaGetSymbolAddress((void**)&hbuf, g_h);
    cudaGetSymbolAddress((void**)&m6, g_m6);

    const int SMEM_ATTN = (3 * 64 * 65 + 64 * 64) * 4;
    cudaFuncSetAttribute(attn_kernel, cudaFuncAttributeMaxDynamicSharedMemorySize, SMEM_ATTN);

    cudaMemcpyAsync(x, video, (size_t)SV * D_MODEL * sizeof(float), cudaMemcpyDeviceToDevice);
    cudaMemcpyAsync(x + (size_t)SV * D_MODEL, action, (size_t)SA * D_MODEL * sizeof(float),
                    cudaMemcpyDeviceToDevice);

    for (int l = 0; l < NL; l++) {
        m6_kernel<<<(2 * 6 * D_MODEL + 255) / 256, 256>>>(mod, vtmod, atmod, m6, l);
        lnmod_kernel<<<S_TOT, 256>>>(x, a, m6, 0, 1);

        for (int e = 0; e < 2; e++) {
            int M = e ? SA : SV;
            size_t roff = e ? (size_t)SV * D_MODEL : 0;
            size_t woff = (size_t)(e * NL + l) * D_MODEL * D_MODEL;
            size_t boff = (size_t)(e * NL + l) * D_MODEL;
            dim3 g(D_MODEL / 128, M / 128);
            sgemm_kernel<0><<<g, 256>>>(a + roff, Wq + woff, bq + boff, q + roff, nullptr, nullptr, M, D_MODEL, D_MODEL);
            sgemm_kernel<0><<<g, 256>>>(a + roff, Wk + woff, bk + boff, k + roff, nullptr, nullptr, M, D_MODEL, D_MODEL);
            sgemm_kernel<0><<<g, 256>>>(a + roff, Wv + woff, bv + boff, v + roff, nullptr, nullptr, M, D_MODEL, D_MODEL);
        }
        rmsrope_kernel<<<S_TOT, 256>>>(q, gq, vfreq, afreq, l);
        rmsrope_kernel<<<S_TOT, 256>>>(k, gk, vfreq, afreq, l);

        attn_kernel<<<dim3(NH, S_TOT / 64), 256, SMEM_ATTN>>>(q, k, v, o);

        for (int e = 0; e < 2; e++) {
            int M = e ? SA : SV;
            size_t roff = e ? (size_t)SV * D_MODEL : 0;
            size_t woff = (size_t)(e * NL + l) * D_MODEL * D_MODEL;
            size_t boff = (size_t)(e * NL + l) * D_MODEL;
            dim3 g(D_MODEL / 128, M / 128);
            sgemm_kernel<2><<<g, 256>>>(o + roff, Wo + woff, bo + boff, x + roff,
                                        x + roff, m6 + (size_t)(e * 6 + 2) * D_MODEL, M, D_MODEL, D_MODEL);
        }

        lnmod_kernel<<<S_TOT, 256>>>(x, a, m6, 3, 4);

        for (int e = 0; e < 2; e++) {
            int M = e ? SA : SV;
            size_t roff = e ? (size_t)SV * D_MODEL : 0;
            size_t hoff = e ? (size_t)SV * FF : 0;
            size_t w1off = (size_t)(e * NL + l) * D_MODEL * FF;
            size_t b1off = (size_t)(e * NL + l) * FF;
            size_t w2off = (size_t)(e * NL + l) * FF * D_MODEL;
            size_t b2off = (size_t)(e * NL + l) * D_MODEL;
            dim3 g1(FF / 128, M / 128);
            sgemm_kernel<1><<<g1, 256>>>(a + roff, W1 + w1off, b1 + b1off, hbuf + hoff,
                                         nullptr, nullptr, M, FF, D_MODEL);
            dim3 g2(D_MODEL / 128, M / 128);
            sgemm_kernel<2><<<g2, 256>>>(hbuf + hoff, W2 + w2off, b2 + b2off, x + roff,
                                         x + roff, m6 + (size_t)(e * 6 + 5) * D_MODEL, M, D_MODEL, FF);
        }
    }

    cudaMemcpyAsync(out, x, (size_t)S_TOT * D_MODEL * sizeof(float), cudaMemcpyDeviceToDevice);
}

// round 4
// speedup vs baseline: 2.2068x; 2.1955x over previous
#include <cuda_runtime.h>
#include <math.h>
#include <stdint.h>

#define SV 2048
#define SA 512
#define S_TOT 2560
#define D_MODEL 1024
#define NH 16
#define DH 64
#define FF 4096
#define NL 2

__device__ float g_x[S_TOT * D_MODEL];
__device__ float g_a[S_TOT * D_MODEL];
__device__ float g_q[S_TOT * D_MODEL];
__device__ float g_k[S_TOT * D_MODEL];
__device__ float g_v[S_TOT * D_MODEL];
__device__ float g_vt[D_MODEL * S_TOT];
__device__ float g_o[S_TOT * D_MODEL];
__device__ float g_h[S_TOT * FF];
__device__ float g_m6[2 * 6 * D_MODEL];
__device__ float g_sc[(size_t)NH * S_TOT * S_TOT];
__device__ float g_wqt[NL * 2 * D_MODEL * D_MODEL];
__device__ float g_wkt[NL * 2 * D_MODEL * D_MODEL];
__device__ float g_wvt[NL * 2 * D_MODEL * D_MODEL];
__device__ float g_wot[NL * 2 * D_MODEL * D_MODEL];
__device__ float g_w1t[(size_t)NL * 2 * D_MODEL * FF];
__device__ float g_w2t[(size_t)NL * 2 * FF * D_MODEL];

__device__ __forceinline__ float tf32r(float f) {
    uint32_t u; asm("cvt.rna.tf32.f32 %0, %1;" : "=r"(u) : "f"(f));
    return __uint_as_float(u);
}
__device__ __forceinline__ void mma8(float* d, const uint32_t* a, const uint32_t* b) {
    asm volatile("mma.sync.aligned.m16n8k8.row.col.f32.tf32.tf32.f32 "
        "{%0,%1,%2,%3}, {%4,%5,%6,%7}, {%8,%9}, {%0,%1,%2,%3};"
        : "+f"(d[0]), "+f"(d[1]), "+f"(d[2]), "+f"(d[3])
        : "r"(a[0]), "r"(a[1]), "r"(a[2]), "r"(a[3]), "r"(b[0]), "r"(b[1]));
}

__device__ __forceinline__ void blockReduce2(float& s, float& ss) {
    __shared__ float bufs[8], bufss[8];
    #pragma unroll
    for (int o = 16; o; o >>= 1) {
        s += __shfl_xor_sync(~0u, s, o); ss += __shfl_xor_sync(~0u, ss, o);
    }
    int w = threadIdx.x >> 5;
    if ((threadIdx.x & 31) == 0) { bufs[w] = s; bufss[w] = ss; }
    __syncthreads();
    if (threadIdx.x < 32) {
        s = (threadIdx.x < 8) ? bufs[threadIdx.x] : 0.f;
        ss = (threadIdx.x < 8) ? bufss[threadIdx.x] : 0.f;
        #pragma unroll
        for (int o = 4; o; o >>= 1) {
            s += __shfl_xor_sync(~0u, s, o); ss += __shfl_xor_sync(~0u, ss, o);
        }
        if (threadIdx.x == 0) { bufs[0] = s; bufss[0] = ss; }
    }
    __syncthreads();
    s = bufs[0]; ss = bufss[0];
}

__global__ void m6_kernel(const float* __restrict__ mod, const float* __restrict__ vt,
                          const float* __restrict__ at, float* __restrict__ m6, int l) {
    int idx = blockIdx.x * blockDim.x + threadIdx.x;
    if (idx >= 2 * 6 * D_MODEL) return;
    int e = idx / (6 * D_MODEL);
    int rem = idx % (6 * D_MODEL);
    m6[idx] = mod[((size_t)(e * NL + l) * 6) * D_MODEL + rem] + (e ? at[rem] : vt[rem]);
}

__global__ void __launch_bounds__(256) lnmod_kernel(const float* __restrict__ x, float* __restrict__ a,
                                                    const float* __restrict__ m6, int jsh, int jsc) {
    int row = blockIdx.x;
    int e = (row >= SV) ? 1 : 0;
    const float4* shv4 = (const float4*)(m6 + (size_t)(e * 6 + jsh) * D_MODEL);
    const float4* scv4 = (const float4*)(m6 + (size_t)(e * 6 + jsc) * D_MODEL);
    float4 v = ((const float4*)(x + (size_t)row * D_MODEL))[threadIdx.x];
    float s = v.x + v.y + v.z + v.w;
    float ss = v.x * v.x + v.y * v.y + v.z * v.z + v.w * v.w;
    blockReduce2(s, ss);
    float mu = s * (1.f / D_MODEL);
    float var = ss * (1.f / D_MODEL) - mu * mu;
    float r = rsqrtf(var + 1e-6f);
    float4 sh = shv4[threadIdx.x], sc = scv4[threadIdx.x];
    float4 o;
    o.x = (v.x - mu) * r * (1.f + sc.x) + sh.x;
    o.y = (v.y - mu) * r * (1.f + sc.y) + sh.y;
    o.z = (v.z - mu) * r * (1.f + sc.z) + sh.z;
    o.w = (v.w - mu) * r * (1.f + sc.w) + sh.w;
    ((float4*)(a + (size_t)row * D_MODEL))[threadIdx.x] = o;
}

__global__ void __launch_bounds__(256) rmsrope_kernel(float* __restrict__ q, const float* __restrict__ gbase,
                                                      const float* __restrict__ vfreq, const float* __restrict__ afreq,
                                                      int l) {
    int row = blockIdx.x;
    int e = (row >= SV) ? 1 : 0;
    int pos = e ? row - SV : row;
    const float* fr = e ? (afreq + (size_t)pos * (DH / 2)) : (vfreq + (size_t)pos * (DH / 2));
    const float* g = gbase + (size_t)(e * NL + l) * D_MODEL;
    float4 v = ((const float4*)(q + (size_t)row * D_MODEL))[threadIdx.x];
    float ss = v.x * v.x + v.y * v.y + v.z * v.z + v.w * v.w, dummy = 0.f;
    blockReduce2(ss, dummy);
    float r = rsqrtf(ss * (1.f / D_MODEL) + 1e-6f);
    float4 gv = ((const float4*)g)[threadIdx.x];
    int d0 = threadIdx.x * 4;
    int j0 = (d0 & (DH - 1)) >> 1, j1 = j0 + 1;
    float c0 = cosf(fr[j0]), s0 = sinf(fr[j0]);
    float c1 = cosf(fr[j1]), s1 = sinf(fr[j1]);
    float xe0 = v.x * r * gv.x, xo0 = v.y * r * gv.y;
    float xe1 = v.z * r * gv.z, xo1 = v.w * r * gv.w;
    float4 o;
    o.x = xe0 * c0 - xo0 * s0; o.y = xe0 * s0 + xo0 * c0;
    o.z = xe1 * c1 - xo1 * s1; o.w = xe1 * s1 + xo1 * c1;
    ((float4*)(q + (size_t)row * D_MODEL))[threadIdx.x] = o;
}

__global__ void __launch_bounds__(256) transpose_kernel(const float* __restrict__ src, float* __restrict__ dst,
                                                        int R, int C) {
    __shared__ float t[32][33];
    int bx = blockIdx.x * 32, by = blockIdx.y * 32;
    for (int i = threadIdx.y; i < 32; i += 8)
        t[i][threadIdx.x] = src[(size_t)(by + i) * C + bx + threadIdx.x];
    __syncthreads();
    for (int i = threadIdx.y; i < 32; i += 8)
        dst[(size_t)(bx + i) * R + by + threadIdx.x] = t[threadIdx.x][i];
}

__global__ void __launch_bounds__(256) softmax_kernel(float* __restrict__ sc) {
    __shared__ float red[8];
    float* row = sc + (size_t)blockIdx.x * S_TOT;
    int t = threadIdx.x;
    float v[10], m = -1e30f;
    #pragma unroll
    for (int i = 0; i < 10; i++) { v[i] = row[t + 256 * i]; m = fmaxf(m, v[i]); }
    #pragma unroll
    for (int o = 16; o; o >>= 1) m = fmaxf(m, __shfl_xor_sync(~0u, m, o));
    if ((t & 31) == 0) red[t >> 5] = m;
    __syncthreads();
    if (t < 32) {
        m = (t < 8) ? red[t] : -1e30f;
        #pragma unroll
        for (int o = 4; o; o >>= 1) m = fmaxf(m, __shfl_xor_sync(~0u, m, o));
        if (t == 0) red[0] = m;
    }
    __syncthreads();
    m = red[0];
    __syncthreads();
    float s = 0.f;
    #pragma unroll
    for (int i = 0; i < 10; i++) { v[i] = expf(v[i] - m); s += v[i]; }
    #pragma unroll
    for (int o = 16; o; o >>= 1) s += __shfl_xor_sync(~0u, s, o);
    if ((t & 31) == 0) red[t >> 5] = s;
    __syncthreads();
    if (t < 32) {
        s = (t < 8) ? red[t] : 0.f;
        #pragma unroll
        for (int o = 4; o; o >>= 1) s += __shfl_xor_sync(~0u, s, o);
        if (t == 0) red[0] = s;
    }
    __syncthreads();
    float inv = 1.f / red[0];
    #pragma unroll
    for (int i = 0; i < 10; i++) row[t + 256 * i] = v[i] * inv;
}

// ---------- mma.sync 3xTF32 GEMM: C[M,N] = epi(A[M,K] @ Bt[N,K]^T) ----------
// BM=128, BK=16. BN template (128 -> 256 thr, 64 -> 128 thr).
// EPI 0:+bias  1:gelu(+bias)  2:res+gate*(+bias)  3:*0.125+structural mask  4:plain
template <int BN, int EPI>
__global__ void __launch_bounds__((BN == 128) ? 256 : 128) tgemm(
    const float* __restrict__ A, const float* __restrict__ Bt,
    const float* __restrict__ bias, float* __restrict__ C,
    const float* __restrict__ res, const float* __restrict__ gate,
    int K, int lda, int ldb, int ldc, size_t za, size_t zb, size_t zc) {
    constexpr int THREADS = (BN == 128) ? 256 : 128;
    constexpr int NF4 = 512 + BN * 4;          // float4 count per stage (A:512, B:BN*4)
    constexpr int NPF = NF4 / THREADS;
    constexpr int AHI = 0, ALO = 2560, BHI = 5120, BLO = 5120 + BN * 20;
    constexpr int STG = 5120 + BN * 40;        // floats per stage
    constexpr int WX = BN / 32;

    extern __shared__ float smf[];
    int tid = threadIdx.x;
    int wid = tid >> 5, lane = tid & 31;
    int wy = wid / WX, wx = wid % WX;
    int r = lane >> 2, cq = lane & 3;

    A  += (size_t)blockIdx.z * za + (size_t)blockIdx.y * 128 * lda;
    Bt += (size_t)blockIdx.z * zb + (size_t)blockIdx.x * BN * ldb;
    C  += (size_t)blockIdx.z * zc;

    float acc[4][4][4];
    #pragma unroll
    for (int i = 0; i < 4; i++)
        #pragma unroll
        for (int j = 0; j < 4; j++)
            #pragma unroll
            for (int t = 0; t < 4; t++) acc[i][j][t] = 0.f;

    float4 pf[NPF];

    auto loadG = [&](int c) {
        #pragma unroll
        for (int t = 0; t < NPF; t++) {
            int idx = tid + t * THREADS;
            const float* src;
            if (idx < 512) src = A  + (size_t)(idx >> 2) * lda + c * 16 + (idx & 3) * 4;
            else { int bi = idx - 512; src = Bt + (size_t)(bi >> 2) * ldb + c * 16 + (bi & 3) * 4; }
            pf[t] = *(const float4*)src;
        }
    };
    auto storeS = [&](int s) {
        float* base = smf + s * STG;
        #pragma unroll
        for (int t = 0; t < NPF; t++) {
            float4 f = pf[t];
            float4 h, l;
            h.x = tf32r(f.x); l.x = tf32r(f.x - h.x);
            h.y = tf32r(f.y); l.y = tf32r(f.y - h.y);
            h.z = tf32r(f.z); l.z = tf32r(f.z - h.z);
            h.w = tf32r(f.w); l.w = tf32r(f.w - h.w);
            int idx = tid + t * THREADS;
            float* dst;
            int losz;
            if (idx < 512) { dst = base + AHI + (idx >> 2) * 20 + (idx & 3) * 4; losz = ALO - AHI; }
            else { int bi = idx - 512; dst = base + BHI + (bi >> 2) * 20 + (bi & 3) * 4; losz = BLO - BHI; }
            *(float4*)dst = h;
            *(float4*)(dst + losz) = l;
        }
    };
    auto compute = [&](int s) {
        const uint32_t* base = (const uint32_t*)(smf + s * STG);
        #pragma unroll
        for (int k8 = 0; k8 < 2; k8++) {
            int k0 = k8 * 8;
            uint32_t ah[4][4], al[4][4], bh[4][2], bl[4][2];
            #pragma unroll
            for (int i = 0; i < 4; i++) {
                int mrow = wy * 64 + i * 16;
                const uint32_t* ph = base + AHI + (mrow + r) * 20 + k0 + cq;
                ah[i][0] = ph[0]; ah[i][1] = ph[8 * 20]; ah[i][2] = ph[4]; ah[i][3] = ph[8 * 20 + 4];
                const uint32_t* pl = base + ALO + (mrow + r) * 20 + k0 + cq;
                al[i][0] = pl[0]; al[i][1] = pl[8 * 20]; al[i][2] = pl[4]; al[i][3] = pl[8 * 20 + 4];
            }
            #pragma unroll
            for (int j = 0; j < 4; j++) {
                int nrow = wx * 32 + j * 8;
                const uint32_t* ph = base + BHI + (nrow + r) * 20 + k0 + cq;
                bh[j][0] = ph[0]; bh[j][1] = ph[4];
                const uint32_t* pl = base + BLO + (nrow + r) * 20 + k0 + cq;
                bl[j][0] = pl[0]; bl[j][1] = pl[4];
            }
            #pragma unroll
            for (int i = 0; i < 4; i++)
                #pragma unroll
                for (int j = 0; j < 4; j++) {
                    mma8(acc[i][j], ah[i], bh[j]);
                    mma8(acc[i][j], al[i], bh[j]);
                    mma8(acc[i][j], ah[i], bl[j]);
                }
        }
    };

    loadG(0);
    storeS(0);
    __syncthreads();
    int NC = K >> 4;
    for (int c = 0; c < NC; c++) {
        if (c + 1 < NC) loadG(c + 1);
        compute(c & 1);
        if (c + 1 < NC) storeS((c + 1) & 1);
        __syncthreads();
    }

    int rowb = blockIdx.y * 128 + wy * 64;
    int colb = blockIdx.x * BN + wx * 32;
    #pragma unroll
    for (int i = 0; i < 4; i++) {
        #pragma unroll
        for (int j = 0; j < 4; j++) {
            int col = colb + j * 8 + cq * 2;
            #pragma unroll
            for (int h = 0; h < 2; h++) {
                int row = rowb + i * 16 + r + h * 8;
                float v0 = acc[i][j][h * 2], v1 = acc[i][j][h * 2 + 1];
                if (EPI <= 2) { v0 += bias[col]; v1 += bias[col + 1]; }
                if (EPI == 1) {
                    float t0 = v0, t1 = v1;
                    v0 = 0.5f * t0 * (1.f + tanhf(0.7978845608028654f * (t0 + 0.044715f * t0 * t0 * t0)));
                    v1 = 0.5f * t1 * (1.f + tanhf(0.7978845608028654f * (t1 + 0.044715f * t1 * t1 * t1)));
                } else if (EPI == 2) {
                    float2 rv = *(const float2*)(res + (size_t)row * ldc + col);
                    v0 = rv.x + gate[col] * v0;
                    v1 = rv.y + gate[col + 1] * v1;
                } else if (EPI == 3) {
                    v0 *= 0.125f; v1 *= 0.125f;
                    bool m0, m1;
                    if (row < SV) { m0 = (col >= SV); m1 = (col + 1 >= SV); }
                    else { m0 = (col > row); m1 = (col + 1 > row); }
                    if (m0) v0 = -1e9f;
                    if (m1) v1 = -1e9f;
                }
                float2 ov; ov.x = v0; ov.y = v1;
                *(float2*)(C + (size_t)row * ldc + col) = ov;
            }
        }
    }
}

extern "C" void kernel_launch(void* const* d_in, const int* in_sizes, int n_in,
                              void* d_out, int out_size) {
    const float* video = (const float*)d_in[0];
    const float* action = (const float*)d_in[1];
    const float* vfreq = (const float*)d_in[2];
    const float* afreq = (const float*)d_in[3];
    const float* vtmod = (const float*)d_in[4];
    const float* atmod = (const float*)d_in[5];
    const float* Wq = (const float*)d_in[6];
    const float* Wk = (const float*)d_in[7];
    const float* Wv = (const float*)d_in[8];
    const float* Wo = (const float*)d_in[9];
    const float* bq = (const float*)d_in[10];
    const float* bk = (const float*)d_in[11];
    const float* bv = (const float*)d_in[12];
    const float* bo = (const float*)d_in[13];
    const float* gq = (const float*)d_in[14];
    const float* gk = (const float*)d_in[15];
    const float* mod = (const float*)d_in[16];
    const float* W1 = (const float*)d_in[17];
    const float* b1 = (const float*)d_in[18];
    const float* W2 = (const float*)d_in[19];
    const float* b2 = (const float*)d_in[20];
    float* out = (float*)d_out;

    float *x, *a, *q, *k, *v, *vt, *o, *hbuf, *m6, *sc;
    float *wqt, *wkt, *wvt, *wot, *w1t, *w2t;
    cudaGetSymbolAddress((void**)&x, g_x);
    cudaGetSymbolAddress((void**)&a, g_a);
    cudaGetSymbolAddress((void**)&q, g_q);
    cudaGetSymbolAddress((void**)&k, g_k);
    cudaGetSymbolAddress((void**)&v, g_v);
    cudaGetSymbolAddress((void**)&vt, g_vt);
    cudaGetSymbolAddress((void**)&o, g_o);
    cudaGetSymbolAddress((void**)&hbuf, g_h);
    cudaGetSymbolAddress((void**)&m6, g_m6);
    cudaGetSymbolAddress((void**)&sc, g_sc);
    cudaGetSymbolAddress((void**)&wqt, g_wqt);
    cudaGetSymbolAddress((void**)&wkt, g_wkt);
    cudaGetSymbolAddress((void**)&wvt, g_wvt);
    cudaGetSymbolAddress((void**)&wot, g_wot);
    cudaGetSymbolAddress((void**)&w1t, g_w1t);
    cudaGetSymbolAddress((void**)&w2t, g_w2t);

    const int SM128 = (5120 + 128 * 40) * 2 * 4;  // 81920 B
    const int SM64  = (5120 + 64 * 40) * 2 * 4;   // 61440 B
    cudaFuncSetAttribute(tgemm<128, 0>, cudaFuncAttributeMaxDynamicSharedMemorySize, SM128);
    cudaFuncSetAttribute(tgemm<128, 1>, cudaFuncAttributeMaxDynamicSharedMemorySize, SM128);
    cudaFuncSetAttribute(tgemm<128, 2>, cudaFuncAttributeMaxDynamicSharedMemorySize, SM128);
    cudaFuncSetAttribute(tgemm<128, 3>, cudaFuncAttributeMaxDynamicSharedMemorySize, SM128);
    cudaFuncSetAttribute(tgemm<64, 4>, cudaFuncAttributeMaxDynamicSharedMemorySize, SM64);

    dim3 tb(32, 8);
    for (int e = 0; e < 2; e++)
        for (int l = 0; l < NL; l++) {
            size_t off = (size_t)(e * NL + l) * D_MODEL * D_MODEL;
            dim3 gdd(D_MODEL / 32, D_MODEL / 32);
            transpose_kernel<<<gdd, tb>>>(Wq + off, wqt + off, D_MODEL, D_MODEL);
            transpose_kernel<<<gdd, tb>>>(Wk + off, wkt + off, D_MODEL, D_MODEL);
            transpose_kernel<<<gdd, tb>>>(Wv + off, wvt + off, D_MODEL, D_MODEL);
            transpose_kernel<<<gdd, tb>>>(Wo + off, wot + off, D_MODEL, D_MODEL);
            size_t off1 = (size_t)(e * NL + l) * D_MODEL * FF;
            transpose_kernel<<<dim3(FF / 32, D_MODEL / 32), tb>>>(W1 + off1, w1t + off1, D_MODEL, FF);
            transpose_kernel<<<dim3(D_MODEL / 32, FF / 32), tb>>>(W2 + off1, w2t + off1, FF, D_MODEL);
        }

    cudaMemcpyAsync(x, video, (size_t)SV * D_MODEL * 4, cudaMemcpyDeviceToDevice);
    cudaMemcpyAsync(x + (size_t)SV * D_MODEL, action, (size_t)SA * D_MODEL * 4, cudaMemcpyDeviceToDevice);

    for (int l = 0; l < NL; l++) {
        m6_kernel<<<48, 256>>>(mod, vtmod, atmod, m6, l);
        lnmod_kernel<<<S_TOT, 256>>>(x, a, m6, 0, 1);

        for (int e = 0; e < 2; e++) {
            int M = e ? SA : SV;
            size_t roff = e ? (size_t)SV * D_MODEL : 0;
            size_t woff = (size_t)(e * NL + l) * D_MODEL * D_MODEL;
            size_t boff = (size_t)(e * NL + l) * D_MODEL;
            dim3 g(D_MODEL / 128, M / 128);
            tgemm<128, 0><<<g, 256, SM128>>>(a + roff, wqt + woff, bq + boff, q + roff,
                nullptr, nullptr, D_MODEL, D_MODEL, D_MODEL, D_MODEL, 0, 0, 0);
            tgemm<128, 0><<<g, 256, SM128>>>(a + roff, wkt + woff, bk + boff, k + roff,
                nullptr, nullptr, D_MODEL, D_MODEL, D_MODEL, D_MODEL, 0, 0, 0);
            tgemm<128, 0><<<g, 256, SM128>>>(a + roff, wvt + woff, bv + boff, v + roff,
                nullptr, nullptr, D_MODEL, D_MODEL, D_MODEL, D_MODEL, 0, 0, 0);
        }
        rmsrope_kernel<<<S_TOT, 256>>>(q, gq, vfreq, afreq, l);
        rmsrope_kernel<<<S_TOT, 256>>>(k, gk, vfreq, afreq, l);

        tgemm<128, 3><<<dim3(S_TOT / 128, S_TOT / 128, NH), 256, SM128>>>(
            q, k, nullptr, sc, nullptr, nullptr,
            DH, D_MODEL, D_MODEL, S_TOT, (size_t)DH, (size_t)DH, (size_t)S_TOT * S_TOT);
        softmax_kernel<<<NH * S_TOT, 256>>>(sc);
        transpose_kernel<<<dim3(D_MODEL / 32, S_TOT / 32), tb>>>(v, vt, S_TOT, D_MODEL);
        tgemm<64, 4><<<dim3(1, S_TOT / 128, NH), 128, SM64>>>(
            sc, vt, nullptr, o, nullptr, nullptr,
            S_TOT, S_TOT, S_TOT, D_MODEL,
            (size_t)S_TOT * S_TOT, (size_t)DH * S_TOT, (size_t)DH);

        for (int e = 0; e < 2; e++) {
            int M = e ? SA : SV;
            size_t roff = e ? (size_t)SV * D_MODEL : 0;
            size_t woff = (size_t)(e * NL + l) * D_MODEL * D_MODEL;
            size_t boff = (size_t)(e * NL + l) * D_MODEL;
            dim3 g(D_MODEL / 128, M / 128);
            tgemm<128, 2><<<g, 256, SM128>>>(o + roff, wot + woff, bo + boff, x + roff,
                x + roff, m6 + (size_t)(e * 6 + 2) * D_MODEL,
                D_MODEL, D_MODEL, D_MODEL, D_MODEL, 0, 0, 0);
        }

        lnmod_kernel<<<S_TOT, 256>>>(x, a, m6, 3, 4);

        for (int e = 0; e < 2; e++) {
            int M = e ? SA : SV;
            size_t roff = e ? (size_t)SV * D_MODEL : 0;
            size_t hoff = e ? (size_t)SV * FF : 0;
            size_t w1off = (size_t)(e * NL + l) * D_MODEL * FF;
            size_t b1off = (size_t)(e * NL + l) * FF;
            size_t b2off = (size_t)(e * NL + l) * D_MODEL;
            tgemm<128, 1><<<dim3(FF / 128, M / 128), 256, SM128>>>(
                a + roff, w1t + w1off, b1 + b1off, hbuf + hoff,
                nullptr, nullptr, D_MODEL, D_MODEL, D_MODEL, FF, 0, 0, 0);
            tgemm<128, 2><<<dim3(D_MODEL / 128, M / 128), 256, SM128>>>(
                hbuf + hoff, w2t + w1off, b2 + b2off, x + roff,
                x + roff, m6 + (size_t)(e * 6 + 5) * D_MODEL,
                FF, FF, FF, D_MODEL, 0, 0, 0);
        }
    }

    cudaMemcpyAsync(out, x, (size_t)S_TOT * D_MODEL * 4, cudaMemcpyDeviceToDevice);
}

// round 5
// speedup vs baseline: 4.0082x; 1.8163x over previous
#include <cuda_runtime.h>
#include <cuda_bf16.h>
#include <math.h>
#include <stdint.h>

#define SV 2048
#define SA 512
#define S_TOT 2560
#define D_MODEL 1024
#define NH 16
#define DH 64
#define FF 4096
#define NL 2

__device__ float g_x[S_TOT * D_MODEL];
__device__ float g_a[S_TOT * D_MODEL];
__device__ float g_q[S_TOT * D_MODEL];
__device__ float g_k[S_TOT * D_MODEL];
__device__ float g_v[S_TOT * D_MODEL];
__device__ float g_vt[D_MODEL * S_TOT];
__device__ float g_o[S_TOT * D_MODEL];
__device__ float g_h[S_TOT * FF];
__device__ float g_m6[2 * 6 * D_MODEL];
__device__ float g_sc[(size_t)NH * S_TOT * S_TOT];
__device__ float g_wqt[NL * 2 * D_MODEL * D_MODEL];
__device__ float g_wkt[NL * 2 * D_MODEL * D_MODEL];
__device__ float g_wvt[NL * 2 * D_MODEL * D_MODEL];
__device__ float g_wot[NL * 2 * D_MODEL * D_MODEL];
__device__ float g_w1t[(size_t)NL * 2 * D_MODEL * FF];
__device__ float g_w2t[(size_t)NL * 2 * FF * D_MODEL];

__device__ __forceinline__ void mma16(float* d, const uint32_t* a, const uint32_t* b) {
    asm volatile("mma.sync.aligned.m16n8k16.row.col.f32.bf16.bf16.f32 "
        "{%0,%1,%2,%3}, {%4,%5,%6,%7}, {%8,%9}, {%0,%1,%2,%3};"
        : "+f"(d[0]), "+f"(d[1]), "+f"(d[2]), "+f"(d[3])
        : "r"(a[0]), "r"(a[1]), "r"(a[2]), "r"(a[3]), "r"(b[0]), "r"(b[1]));
}

__device__ __forceinline__ void blockReduce2(float& s, float& ss) {
    __shared__ float bufs[8], bufss[8];
    #pragma unroll
    for (int o = 16; o; o >>= 1) {
        s += __shfl_xor_sync(~0u, s, o); ss += __shfl_xor_sync(~0u, ss, o);
    }
    int w = threadIdx.x >> 5;
    if ((threadIdx.x & 31) == 0) { bufs[w] = s; bufss[w] = ss; }
    __syncthreads();
    if (threadIdx.x < 32) {
        s = (threadIdx.x < 8) ? bufs[threadIdx.x] : 0.f;
        ss = (threadIdx.x < 8) ? bufss[threadIdx.x] : 0.f;
        #pragma unroll
        for (int o = 4; o; o >>= 1) {
            s += __shfl_xor_sync(~0u, s, o); ss += __shfl_xor_sync(~0u, ss, o);
        }
        if (threadIdx.x == 0) { bufs[0] = s; bufss[0] = ss; }
    }
    __syncthreads();
    s = bufs[0]; ss = bufss[0];
}

__global__ void m6_kernel(const float* __restrict__ mod, const float* __restrict__ vt,
                          const float* __restrict__ at, float* __restrict__ m6, int l) {
    int idx = blockIdx.x * blockDim.x + threadIdx.x;
    if (idx >= 2 * 6 * D_MODEL) return;
    int e = idx / (6 * D_MODEL);
    int rem = idx % (6 * D_MODEL);
    m6[idx] = mod[((size_t)(e * NL + l) * 6) * D_MODEL + rem] + (e ? at[rem] : vt[rem]);
}

__global__ void __launch_bounds__(256) lnmod_kernel(const float* __restrict__ x, float* __restrict__ a,
                                                    const float* __restrict__ m6, int jsh, int jsc) {
    int row = blockIdx.x;
    int e = (row >= SV) ? 1 : 0;
    const float4* shv4 = (const float4*)(m6 + (size_t)(e * 6 + jsh) * D_MODEL);
    const float4* scv4 = (const float4*)(m6 + (size_t)(e * 6 + jsc) * D_MODEL);
    float4 v = ((const float4*)(x + (size_t)row * D_MODEL))[threadIdx.x];
    float s = v.x + v.y + v.z + v.w;
    float ss = v.x * v.x + v.y * v.y + v.z * v.z + v.w * v.w;
    blockReduce2(s, ss);
    float mu = s * (1.f / D_MODEL);
    float var = ss * (1.f / D_MODEL) - mu * mu;
    float r = rsqrtf(var + 1e-6f);
    float4 sh = shv4[threadIdx.x], sc = scv4[threadIdx.x];
    float4 o;
    o.x = (v.x - mu) * r * (1.f + sc.x) + sh.x;
    o.y = (v.y - mu) * r * (1.f + sc.y) + sh.y;
    o.z = (v.z - mu) * r * (1.f + sc.z) + sh.z;
    o.w = (v.w - mu) * r * (1.f + sc.w) + sh.w;
    ((float4*)(a + (size_t)row * D_MODEL))[threadIdx.x] = o;
}

__global__ void __launch_bounds__(256) rmsrope_kernel(float* __restrict__ q, const float* __restrict__ gbase,
                                                      const float* __restrict__ vfreq, const float* __restrict__ afreq,
                                                      int l) {
    int row = blockIdx.x;
    int e = (row >= SV) ? 1 : 0;
    int pos = e ? row - SV : row;
    const float* fr = e ? (afreq + (size_t)pos * (DH / 2)) : (vfreq + (size_t)pos * (DH / 2));
    const float* g = gbase + (size_t)(e * NL + l) * D_MODEL;
    float4 v = ((const float4*)(q + (size_t)row * D_MODEL))[threadIdx.x];
    float ss = v.x * v.x + v.y * v.y + v.z * v.z + v.w * v.w, dummy = 0.f;
    blockReduce2(ss, dummy);
    float r = rsqrtf(ss * (1.f / D_MODEL) + 1e-6f);
    float4 gv = ((const float4*)g)[threadIdx.x];
    int d0 = threadIdx.x * 4;
    int j0 = (d0 & (DH - 1)) >> 1, j1 = j0 + 1;
    float c0 = cosf(fr[j0]), s0 = sinf(fr[j0]);
    float c1 = cosf(fr[j1]), s1 = sinf(fr[j1]);
    float xe0 = v.x * r * gv.x, xo0 = v.y * r * gv.y;
    float xe1 = v.z * r * gv.z, xo1 = v.w * r * gv.w;
    float4 o;
    o.x = xe0 * c0 - xo0 * s0; o.y = xe0 * s0 + xo0 * c0;
    o.z = xe1 * c1 - xo1 * s1; o.w = xe1 * s1 + xo1 * c1;
    ((float4*)(q + (size_t)row * D_MODEL))[threadIdx.x] = o;
}

__global__ void __launch_bounds__(256) transpose_kernel(const float* __restrict__ src, float* __restrict__ dst,
                                                        int R, int C) {
    __shared__ float t[32][33];
    int bx = blockIdx.x * 32, by = blockIdx.y * 32;
    for (int i = threadIdx.y; i < 32; i += 8)
        t[i][threadIdx.x] = src[(size_t)(by + i) * C + bx + threadIdx.x];
    __syncthreads();
    for (int i = threadIdx.y; i < 32; i += 8)
        dst[(size_t)(bx + i) * R + by + threadIdx.x] = t[threadIdx.x][i];
}

// softmax over variable row length; len = SV for video rows, q0+128 for action rows.
__global__ void __launch_bounds__(256) softmax_kernel(float* __restrict__ sc) {
    __shared__ float red[8];
    int qrow = blockIdx.x % S_TOT;
    int len = (qrow < SV) ? SV : (((qrow >> 7) << 7) + 128);
    float* row = sc + (size_t)blockIdx.x * S_TOT;
    int t = threadIdx.x;
    float v[10], m = -1e30f;
    #pragma unroll
    for (int i = 0; i < 10; i++) {
        int idx = t + 256 * i;
        v[i] = (idx < len) ? row[idx] : -1e30f;
        m = fmaxf(m, v[i]);
    }
    #pragma unroll
    for (int o = 16; o; o >>= 1) m = fmaxf(m, __shfl_xor_sync(~0u, m, o));
    if ((t & 31) == 0) red[t >> 5] = m;
    __syncthreads();
    if (t < 32) {
        m = (t < 8) ? red[t] : -1e30f;
        #pragma unroll
        for (int o = 4; o; o >>= 1) m = fmaxf(m, __shfl_xor_sync(~0u, m, o));
        if (t == 0) red[0] = m;
    }
    __syncthreads();
    m = red[0];
    __syncthreads();
    float s = 0.f;
    #pragma unroll
    for (int i = 0; i < 10; i++) {
        int idx = t + 256 * i;
        v[i] = (idx < len) ? expf(v[i] - m) : 0.f;
        s += v[i];
    }
    #pragma unroll
    for (int o = 16; o; o >>= 1) s += __shfl_xor_sync(~0u, s, o);
    if ((t & 31) == 0) red[t >> 5] = s;
    __syncthreads();
    if (t < 32) {
        s = (t < 8) ? red[t] : 0.f;
        #pragma unroll
        for (int o = 4; o; o >>= 1) s += __shfl_xor_sync(~0u, s, o);
        if (t == 0) red[0] = s;
    }
    __syncthreads();
    float inv = 1.f / red[0];
    #pragma unroll
    for (int i = 0; i < 10; i++) {
        int idx = t + 256 * i;
        if (idx < len) row[idx] = v[i] * inv;
    }
}

// ---------- mma.sync 3-term BF16-split GEMM: C[M,N] = epi(A[M,K] @ Bt[N,K]^T) ----------
// BM=128, BK=32. BN=128 -> 256 thr; BN=64 -> 128 thr.
// EPI 0:+bias 1:gelu(+bias) 2:res+gate*(+bias) 3:*0.125+mask(+tile skip) 4:plain(+K clip)
template <int BN, int EPI>
__global__ void __launch_bounds__((BN == 128) ? 256 : 128) tgemm(
    const float* __restrict__ A, const float* __restrict__ Bt,
    const float* __restrict__ bias, float* __restrict__ C,
    const float* __restrict__ res, const float* __restrict__ gate,
    int K, int lda, int ldb, int ldc, size_t za, size_t zb, size_t zc) {
    constexpr int THREADS = (BN == 128) ? 256 : 128;
    constexpr int NF4 = (128 + BN) * 8;        // float4 per stage (A:1024, B:BN*8)
    constexpr int NPF = NF4 / THREADS;
    // word (u32) offsets inside a stage
    constexpr int AHI = 0, AMI = 2560, BHIo = 5120, BMIo = 5120 + BN * 20;
    constexpr int STG = 5120 + BN * 40;        // u32 words per stage
    constexpr int WX = BN / 32;

    if (EPI == 3) {
        int q0 = blockIdx.y * 128, k0 = blockIdx.x * 128;
        if (q0 < SV && k0 >= SV) return;       // video q never sees action k
        if (q0 >= SV && k0 > q0) return;       // strictly above diagonal (block level)
    }
    if (EPI == 4) {
        int q0 = blockIdx.y * 128;
        K = (q0 < SV) ? SV : (q0 + 128);       // clip K to valid keys
    }

    extern __shared__ uint32_t smw[];
    int tid = threadIdx.x;
    int wid = tid >> 5, lane = tid & 31;
    int wy = wid / WX, wx = wid % WX;
    int r = lane >> 2, cq = lane & 3;

    A  += (size_t)blockIdx.z * za + (size_t)blockIdx.y * 128 * lda;
    Bt += (size_t)blockIdx.z * zb + (size_t)blockIdx.x * BN * ldb;
    C  += (size_t)blockIdx.z * zc;

    float acc[4][4][4];
    #pragma unroll
    for (int i = 0; i < 4; i++)
        #pragma unroll
        for (int j = 0; j < 4; j++)
            #pragma unroll
            for (int t = 0; t < 4; t++) acc[i][j][t] = 0.f;

    float4 pf[NPF];

    auto loadG = [&](int c) {
        #pragma unroll
        for (int t = 0; t < NPF; t++) {
            int idx = tid + t * THREADS;
            const float* src;
            if (idx < 1024) src = A + (size_t)(idx >> 3) * lda + c * 32 + (idx & 7) * 4;
            else { int bi = idx - 1024; src = Bt + (size_t)(bi >> 3) * ldb + c * 32 + (bi & 7) * 4; }
            pf[t] = *(const float4*)src;
        }
    };
    auto storeS = [&](int s) {
        uint32_t* base = smw + s * STG;
        #pragma unroll
        for (int t = 0; t < NPF; t++) {
            float4 f = pf[t];
            __nv_bfloat162 h01 = __floats2bfloat162_rn(f.x, f.y);
            __nv_bfloat162 h23 = __floats2bfloat162_rn(f.z, f.w);
            __nv_bfloat162 m01 = __floats2bfloat162_rn(f.x - __bfloat162float(h01.x),
                                                       f.y - __bfloat162float(h01.y));
            __nv_bfloat162 m23 = __floats2bfloat162_rn(f.z - __bfloat162float(h23.x),
                                                       f.w - __bfloat162float(h23.y));
            int idx = tid + t * THREADS;
            uint32_t* dst;
            int mo;
            if (idx < 1024) { dst = base + AHI + (idx >> 3) * 20 + (idx & 7) * 2; mo = AMI - AHI; }
            else { int bi = idx - 1024; dst = base + BHIo + (bi >> 3) * 20 + (bi & 7) * 2; mo = BMIo - BHIo; }
            dst[0] = *(const uint32_t*)&h01;
            dst[1] = *(const uint32_t*)&h23;
            dst[mo] = *(const uint32_t*)&m01;
            dst[mo + 1] = *(const uint32_t*)&m23;
        }
    };
    auto compute = [&](int s) {
        const uint32_t* base = smw + s * STG;
        #pragma unroll
        for (int k16 = 0; k16 < 2; k16++) {
            int kw = k16 * 8;  // word offset of this k16 slice
            uint32_t ah[4][4], am[4][4], bh[4][2], bm[4][2];
            #pragma unroll
            for (int i = 0; i < 4; i++) {
                int mrow = wy * 64 + i * 16 + r;
                const uint32_t* ph = base + AHI + mrow * 20 + kw + cq;
                ah[i][0] = ph[0]; ah[i][1] = ph[8 * 20]; ah[i][2] = ph[4]; ah[i][3] = ph[8 * 20 + 4];
                const uint32_t* pm = base + AMI + mrow * 20 + kw + cq;
                am[i][0] = pm[0]; am[i][1] = pm[8 * 20]; am[i][2] = pm[4]; am[i][3] = pm[8 * 20 + 4];
            }
            #pragma unroll
            for (int j = 0; j < 4; j++) {
                int nrow = wx * 32 + j * 8 + r;
                const uint32_t* ph = base + BHIo + nrow * 20 + kw + cq;
                bh[j][0] = ph[0]; bh[j][1] = ph[4];
                const uint32_t* pm = base + BMIo + nrow * 20 + kw + cq;
                bm[j][0] = pm[0]; bm[j][1] = pm[4];
            }
            #pragma unroll
            for (int i = 0; i < 4; i++)
                #pragma unroll
                for (int j = 0; j < 4; j++) {
                    mma16(acc[i][j], ah[i], bh[j]);
                    mma16(acc[i][j], am[i], bh[j]);
                    mma16(acc[i][j], ah[i], bm[j]);
                }
        }
    };

    loadG(0);
    storeS(0);
    __syncthreads();
    int NC = K >> 5;
    for (int c = 0; c < NC; c++) {
        if (c + 1 < NC) loadG(c + 1);
        compute(c & 1);
        if (c + 1 < NC) storeS((c + 1) & 1);
        __syncthreads();
    }

    int rowb = blockIdx.y * 128 + wy * 64;
    int colb = blockIdx.x * BN + wx * 32;
    #pragma unroll
    for (int i = 0; i < 4; i++) {
        #pragma unroll
        for (int j = 0; j < 4; j++) {
            int col = colb + j * 8 + cq * 2;
            #pragma unroll
            for (int h = 0; h < 2; h++) {
                int row = rowb + i * 16 + r + h * 8;
                float v0 = acc[i][j][h * 2], v1 = acc[i][j][h * 2 + 1];
                if (EPI <= 2) { v0 += bias[col]; v1 += bias[col + 1]; }
                if (EPI == 1) {
                    float t0 = v0, t1 = v1;
                    v0 = 0.5f * t0 * (1.f + tanhf(0.7978845608028654f * (t0 + 0.044715f * t0 * t0 * t0)));
                    v1 = 0.5f * t1 * (1.f + tanhf(0.7978845608028654f * (t1 + 0.044715f * t1 * t1 * t1)));
                } else if (EPI == 2) {
                    float2 rv = *(const float2*)(res + (size_t)row * ldc + col);
                    v0 = rv.x + gate[col] * v0;
                    v1 = rv.y + gate[col + 1] * v1;
                } else if (EPI == 3) {
                    v0 *= 0.125f; v1 *= 0.125f;
                    bool m0, m1;
                    if (row < SV) { m0 = (col >= SV); m1 = (col + 1 >= SV); }
                    else { m0 = (col > row); m1 = (col + 1 > row); }
                    if (m0) v0 = -1e9f;
                    if (m1) v1 = -1e9f;
                }
                float2 ov; ov.x = v0; ov.y = v1;
                *(float2*)(C + (size_t)row * ldc + col) = ov;
            }
        }
    }
}

extern "C" void kernel_launch(void* const* d_in, const int* in_sizes, int n_in,
                              void* d_out, int out_size) {
    const float* video = (const float*)d_in[0];
    const float* action = (const float*)d_in[1];
    const float* vfreq = (const float*)d_in[2];
    const float* afreq = (const float*)d_in[3];
    const float* vtmod = (const float*)d_in[4];
    const float* atmod = (const float*)d_in[5];
    const float* Wq = (const float*)d_in[6];
    const float* Wk = (const float*)d_in[7];
    const float* Wv = (const float*)d_in[8];
    const float* Wo = (const float*)d_in[9];
    const float* bq = (const float*)d_in[10];
    const float* bk = (const float*)d_in[11];
    const float* bv = (const float*)d_in[12];
    const float* bo = (const float*)d_in[13];
    const float* gq = (const float*)d_in[14];
    const float* gk = (const float*)d_in[15];
    const float* mod = (const float*)d_in[16];
    const float* W1 = (const float*)d_in[17];
    const float* b1 = (const float*)d_in[18];
    const float* W2 = (const float*)d_in[19];
    const float* b2 = (const float*)d_in[20];
    float* out = (float*)d_out;

    float *x, *a, *q, *k, *v, *vt, *o, *hbuf, *m6, *sc;
    float *wqt, *wkt, *wvt, *wot, *w1t, *w2t;
    cudaGetSymbolAddress((void**)&x, g_x);
    cudaGetSymbolAddress((void**)&a, g_a);
    cudaGetSymbolAddress((void**)&q, g_q);
    cudaGetSymbolAddress((void**)&k, g_k);
    cudaGetSymbolAddress((void**)&v, g_v);
    cudaGetSymbolAddress((void**)&vt, g_vt);
    cudaGetSymbolAddress((void**)&o, g_o);
    cudaGetSymbolAddress((void**)&hbuf, g_h);
    cudaGetSymbolAddress((void**)&m6, g_m6);
    cudaGetSymbolAddress((void**)&sc, g_sc);
    cudaGetSymbolAddress((void**)&wqt, g_wqt);
    cudaGetSymbolAddress((void**)&wkt, g_wkt);
    cudaGetSymbolAddress((void**)&wvt, g_wvt);
    cudaGetSymbolAddress((void**)&wot, g_wot);
    cudaGetSymbolAddress((void**)&w1t, g_w1t);
    cudaGetSymbolAddress((void**)&w2t, g_w2t);

    const int SM128 = (5120 + 128 * 40) * 2 * 4;  // 81920 B
    const int SM64  = (5120 + 64 * 40) * 2 * 4;   // 61440 B
    cudaFuncSetAttribute(tgemm<128, 0>, cudaFuncAttributeMaxDynamicSharedMemorySize, SM128);
    cudaFuncSetAttribute(tgemm<128, 1>, cudaFuncAttributeMaxDynamicSharedMemorySize, SM128);
    cudaFuncSetAttribute(tgemm<128, 2>, cudaFuncAttributeMaxDynamicSharedMemorySize, SM128);
    cudaFuncSetAttribute(tgemm<128, 3>, cudaFuncAttributeMaxDynamicSharedMemorySize, SM128);
    cudaFuncSetAttribute(tgemm<64, 4>, cudaFuncAttributeMaxDynamicSharedMemorySize, SM64);

    dim3 tb(32, 8);
    for (int e = 0; e < 2; e++)
        for (int l = 0; l < NL; l++) {
            size_t off = (size_t)(e * NL + l) * D_MODEL * D_MODEL;
            dim3 gdd(D_MODEL / 32, D_MODEL / 32);
            transpose_kernel<<<gdd, tb>>>(Wq + off, wqt + off, D_MODEL, D_MODEL);
            transpose_kernel<<<gdd, tb>>>(Wk + off, wkt + off, D_MODEL, D_MODEL);
            transpose_kernel<<<gdd, tb>>>(Wv + off, wvt + off, D_MODEL, D_MODEL);
            transpose_kernel<<<gdd, tb>>>(Wo + off, wot + off, D_MODEL, D_MODEL);
            size_t off1 = (size_t)(e * NL + l) * D_MODEL * FF;
            transpose_kernel<<<dim3(FF / 32, D_MODEL / 32), tb>>>(W1 + off1, w1t + off1, D_MODEL, FF);
            transpose_kernel<<<dim3(D_MODEL / 32, FF / 32), tb>>>(W2 + off1, w2t + off1, FF, D_MODEL);
        }

    cudaMemcpyAsync(x, video, (size_t)SV * D_MODEL * 4, cudaMemcpyDeviceToDevice);
    cudaMemcpyAsync(x + (size_t)SV * D_MODEL, action, (size_t)SA * D_MODEL * 4, cudaMemcpyDeviceToDevice);

    for (int l = 0; l < NL; l++) {
        m6_kernel<<<48, 256>>>(mod, vtmod, atmod, m6, l);
        lnmod_kernel<<<S_TOT, 256>>>(x, a, m6, 0, 1);

        for (int e = 0; e < 2; e++) {
            int M = e ? SA : SV;
            size_t roff = e ? (size_t)SV * D_MODEL : 0;
            size_t woff = (size_t)(e * NL + l) * D_MODEL * D_MODEL;
            size_t boff = (size_t)(e * NL + l) * D_MODEL;
            dim3 g(D_MODEL / 128, M / 128);
            tgemm<128, 0><<<g, 256, SM128>>>(a + roff, wqt + woff, bq + boff, q + roff,
                nullptr, nullptr, D_MODEL, D_MODEL, D_MODEL, D_MODEL, 0, 0, 0);
            tgemm<128, 0><<<g, 256, SM128>>>(a + roff, wkt + woff, bk + boff, k + roff,
                nullptr, nullptr, D_MODEL, D_MODEL, D_MODEL, D_MODEL, 0, 0, 0);
            tgemm<128, 0><<<g, 256, SM128>>>(a + roff, wvt + woff, bv + boff, v + roff,
                nullptr, nullptr, D_MODEL, D_MODEL, D_MODEL, D_MODEL, 0, 0, 0);
        }
        rmsrope_kernel<<<S_TOT, 256>>>(q, gq, vfreq, afreq, l);
        rmsrope_kernel<<<S_TOT, 256>>>(k, gk, vfreq, afreq, l);

        tgemm<128, 3><<<dim3(S_TOT / 128, S_TOT / 128, NH), 256, SM128>>>(
            q, k, nullptr, sc, nullptr, nullptr,
            DH, D_MODEL, D_MODEL, S_TOT, (size_t)DH, (size_t)DH, (size_t)S_TOT * S_TOT);
        softmax_kernel<<<NH * S_TOT, 256>>>(sc);
        transpose_kernel<<<dim3(D_MODEL / 32, S_TOT / 32), tb>>>(v, vt, S_TOT, D_MODEL);
        tgemm<64, 4><<<dim3(1, S_TOT / 128, NH), 128, SM64>>>(
            sc, vt, nullptr, o, nullptr, nullptr,
            S_TOT, S_TOT, S_TOT, D_MODEL,
            (size_t)S_TOT * S_TOT, (size_t)DH * S_TOT, (size_t)DH);

        for (int e = 0; e < 2; e++) {
            int M = e ? SA : SV;
            size_t roff = e ? (size_t)SV * D_MODEL : 0;
            size_t woff = (size_t)(e * NL + l) * D_MODEL * D_MODEL;
            size_t boff = (size_t)(e * NL + l) * D_MODEL;
            dim3 g(D_MODEL / 128, M / 128);
            tgemm<128, 2><<<g, 256, SM128>>>(o + roff, wot + woff, bo + boff, x + roff,
                x + roff, m6 + (size_t)(e * 6 + 2) * D_MODEL,
                D_MODEL, D_MODEL, D_MODEL, D_MODEL, 0, 0, 0);
        }

        lnmod_kernel<<<S_TOT, 256>>>(x, a, m6, 3, 4);

        for (int e = 0; e < 2; e++) {
            int M = e ? SA : SV;
            size_t roff = e ? (size_t)SV * D_MODEL : 0;
            size_t hoff = e ? (size_t)SV * FF : 0;
            size_t w1off = (size_t)(e * NL + l) * D_MODEL * FF;
            size_t b1off = (size_t)(e * NL + l) * FF;
            size_t b2off = (size_t)(e * NL + l) * D_MODEL;
            tgemm<128, 1><<<dim3(FF / 128, M / 128), 256, SM128>>>(
                a + roff, w1t + w1off, b1 + b1off, hbuf + hoff,
                nullptr, nullptr, D_MODEL, D_MODEL, D_MODEL, FF, 0, 0, 0);
            tgemm<128, 2><<<dim3(D_MODEL / 128, M / 128), 256, SM128>>>(
                hbuf + hoff, w2t + w1off, b2 + b2off, x + roff,
                x + roff, m6 + (size_t)(e * 6 + 5) * D_MODEL,
                FF, FF, FF, D_MODEL, 0, 0, 0);
        }
    }

    cudaMemcpyAsync(out, x, (size_t)S_TOT * D_MODEL * 4, cudaMemcpyDeviceToDevice);
}

// round 7
// speedup vs baseline: 4.4072x; 1.0996x over previous
#include <cuda_runtime.h>
#include <cuda_bf16.h>
#include <math.h>
#include <stdint.h>

#define SV 2048
#define SA 512
#define S_TOT 2560
#define D_MODEL 1024
#define NH 16
#define DH 64
#define FF 4096
#define NL 2
#define LOG2E 1.4426950408889634f

__device__ float g_x[S_TOT * D_MODEL];
__device__ float g_a[S_TOT * D_MODEL];
__device__ float g_q[S_TOT * D_MODEL];
__device__ float g_k[S_TOT * D_MODEL];
__device__ float g_v[S_TOT * D_MODEL];
__device__ float g_vt[D_MODEL * S_TOT];
__device__ float g_o[S_TOT * D_MODEL];
__device__ float g_h[S_TOT * FF];
__device__ float g_m6[2 * 6 * D_MODEL];
__device__ float g_wqt[NL * 2 * D_MODEL * D_MODEL];
__device__ float g_wkt[NL * 2 * D_MODEL * D_MODEL];
__device__ float g_wvt[NL * 2 * D_MODEL * D_MODEL];
__device__ float g_wot[NL * 2 * D_MODEL * D_MODEL];
__device__ float g_w1t[(size_t)NL * 2 * D_MODEL * FF];
__device__ float g_w2t[(size_t)NL * 2 * FF * D_MODEL];

__device__ __forceinline__ void mma16(float* d, const uint32_t* a, const uint32_t* b) {
    asm volatile("mma.sync.aligned.m16n8k16.row.col.f32.bf16.bf16.f32 "
        "{%0,%1,%2,%3}, {%4,%5,%6,%7}, {%8,%9}, {%0,%1,%2,%3};"
        : "+f"(d[0]), "+f"(d[1]), "+f"(d[2]), "+f"(d[3])
        : "r"(a[0]), "r"(a[1]), "r"(a[2]), "r"(a[3]), "r"(b[0]), "r"(b[1]));
}

// fast 2^x for x <= 0, FMA-pipe only
__device__ __forceinline__ float fexp2(float x) {
    x = fmaxf(x, -126.f);
    float fl = floorf(x);
    float f = x - fl;
    float p = 1.54035304e-4f;
    p = fmaf(p, f, 1.33335581e-3f);
    p = fmaf(p, f, 9.61812911e-3f);
    p = fmaf(p, f, 5.55041087e-2f);
    p = fmaf(p, f, 2.40226507e-1f);
    p = fmaf(p, f, 6.93147181e-1f);
    p = fmaf(p, f, 1.0f);
    return p * __int_as_float(((int)fl + 127) << 23);
}

__device__ __forceinline__ uint32_t pack_bf2(float a, float b) {
    __nv_bfloat162 t = __floats2bfloat162_rn(a, b);
    return *(const uint32_t*)&t;
}

__device__ __forceinline__ void blockReduce2(float& s, float& ss) {
    __shared__ float bufs[8], bufss[8];
    #pragma unroll
    for (int o = 16; o; o >>= 1) {
        s += __shfl_xor_sync(~0u, s, o); ss += __shfl_xor_sync(~0u, ss, o);
    }
    int w = threadIdx.x >> 5;
    if ((threadIdx.x & 31) == 0) { bufs[w] = s; bufss[w] = ss; }
    __syncthreads();
    if (threadIdx.x < 32) {
        s = (threadIdx.x < 8) ? bufs[threadIdx.x] : 0.f;
        ss = (threadIdx.x < 8) ? bufss[threadIdx.x] : 0.f;
        #pragma unroll
        for (int o = 4; o; o >>= 1) {
            s += __shfl_xor_sync(~0u, s, o); ss += __shfl_xor_sync(~0u, ss, o);
        }
        if (threadIdx.x == 0) { bufs[0] = s; bufss[0] = ss; }
    }
    __syncthreads();
    s = bufs[0]; ss = bufss[0];
}

__global__ void m6_kernel(const float* __restrict__ mod, const float* __restrict__ vt,
                          const float* __restrict__ at, float* __restrict__ m6, int l) {
    int idx = blockIdx.x * blockDim.x + threadIdx.x;
    if (idx >= 2 * 6 * D_MODEL) return;
    int e = idx / (6 * D_MODEL);
    int rem = idx % (6 * D_MODEL);
    m6[idx] = mod[((size_t)(e * NL + l) * 6) * D_MODEL + rem] + (e ? at[rem] : vt[rem]);
}

__global__ void __launch_bounds__(256) lnmod_kernel(const float* __restrict__ x, float* __restrict__ a,
                                                    const float* __restrict__ m6, int jsh, int jsc) {
    int row = blockIdx.x;
    int e = (row >= SV) ? 1 : 0;
    const float4* shv4 = (const float4*)(m6 + (size_t)(e * 6 + jsh) * D_MODEL);
    const float4* scv4 = (const float4*)(m6 + (size_t)(e * 6 + jsc) * D_MODEL);
    float4 v = ((const float4*)(x + (size_t)row * D_MODEL))[threadIdx.x];
    float s = v.x + v.y + v.z + v.w;
    float ss = v.x * v.x + v.y * v.y + v.z * v.z + v.w * v.w;
    blockReduce2(s, ss);
    float mu = s * (1.f / D_MODEL);
    float var = ss * (1.f / D_MODEL) - mu * mu;
    float r = rsqrtf(var + 1e-6f);
    float4 sh = shv4[threadIdx.x], sc = scv4[threadIdx.x];
    float4 o;
    o.x = (v.x - mu) * r * (1.f + sc.x) + sh.x;
    o.y = (v.y - mu) * r * (1.f + sc.y) + sh.y;
    o.z = (v.z - mu) * r * (1.f + sc.z) + sh.z;
    o.w = (v.w - mu) * r * (1.f + sc.w) + sh.w;
    ((float4*)(a + (size_t)row * D_MODEL))[threadIdx.x] = o;
}

__global__ void __launch_bounds__(256) rmsrope_kernel(float* __restrict__ q, const float* __restrict__ gbase,
                                                      const float* __restrict__ vfreq, const float* __restrict__ afreq,
                                                      int l) {
    int row = blockIdx.x;
    int e = (row >= SV) ? 1 : 0;
    int pos = e ? row - SV : row;
    const float* fr = e ? (afreq + (size_t)pos * (DH / 2)) : (vfreq + (size_t)pos * (DH / 2));
    const float* g = gbase + (size_t)(e * NL + l) * D_MODEL;
    float4 v = ((const float4*)(q + (size_t)row * D_MODEL))[threadIdx.x];
    float ss = v.x * v.x + v.y * v.y + v.z * v.z + v.w * v.w, dummy = 0.f;
    blockReduce2(ss, dummy);
    float r = rsqrtf(ss * (1.f / D_MODEL) + 1e-6f);
    float4 gv = ((const float4*)g)[threadIdx.x];
    int d0 = threadIdx.x * 4;
    int j0 = (d0 & (DH - 1)) >> 1, j1 = j0 + 1;
    float c0 = cosf(fr[j0]), s0 = sinf(fr[j0]);
    float c1 = cosf(fr[j1]), s1 = sinf(fr[j1]);
    float xe0 = v.x * r * gv.x, xo0 = v.y * r * gv.y;
    float xe1 = v.z * r * gv.z, xo1 = v.w * r * gv.w;
    float4 o;
    o.x = xe0 * c0 - xo0 * s0; o.y = xe0 * s0 + xo0 * c0;
    o.z = xe1 * c1 - xo1 * s1; o.w = xe1 * s1 + xo1 * c1;
    ((float4*)(q + (size_t)row * D_MODEL))[threadIdx.x] = o;
}

__global__ void __launch_bounds__(256) transpose_kernel(const float* __restrict__ src, float* __restrict__ dst,
                                                        int R, int C) {
    __shared__ float t[32][33];
    int bx = blockIdx.x * 32, by = blockIdx.y * 32;
    for (int i = threadIdx.y; i < 32; i += 8)
        t[i][threadIdx.x] = src[(size_t)(by + i) * C + bx + threadIdx.x];
    __syncthreads();
    for (int i = threadIdx.y; i < 32; i += 8)
        dst[(size_t)(bx + i) * R + by + threadIdx.x] = t[threadIdx.x][i];
}

// ---------------- flash attention (bf16 3-term, online softmax) ----------------
// grid (NH, S_TOT/64), 128 threads. smem row stride = 36 u32 (64 bf16 = 32 words + 4 pad).
#define FST 36
__global__ void __launch_bounds__(128) flash_kernel(
    const float* __restrict__ Q, const float* __restrict__ K,
    const float* __restrict__ Vt, float* __restrict__ O) {
    __shared__ uint32_t sQh[64 * FST], sQm[64 * FST], sKh[64 * FST], sKm[64 * FST],
                        sVh[64 * FST], sVm[64 * FST];
    int h = blockIdx.x;
    int q0 = blockIdx.y * 64;
    int tid = threadIdx.x, wid = tid >> 5, lane = tid & 31;
    int r = lane >> 2, cq = lane & 3;

    // Q tile (scale 1/8 folded in)
    #pragma unroll
    for (int i = 0; i < 8; i++) {
        int idx = tid + i * 128;
        int row = idx >> 4, c4 = idx & 15;
        float4 f = *(const float4*)(Q + (size_t)(q0 + row) * D_MODEL + h * DH + c4 * 4);
        f.x *= 0.125f; f.y *= 0.125f; f.z *= 0.125f; f.w *= 0.125f;
        uint32_t h01 = pack_bf2(f.x, f.y), h23 = pack_bf2(f.z, f.w);
        __nv_bfloat162* H01 = (__nv_bfloat162*)&h01;
        __nv_bfloat162* H23 = (__nv_bfloat162*)&h23;
        uint32_t m01 = pack_bf2(f.x - __bfloat162float(H01->x), f.y - __bfloat162float(H01->y));
        uint32_t m23 = pack_bf2(f.z - __bfloat162float(H23->x), f.w - __bfloat162float(H23->y));
        int o2 = row * FST + c4 * 2;
        sQh[o2] = h01; sQh[o2 + 1] = h23;
        sQm[o2] = m01; sQm[o2 + 1] = m23;
    }

    int row0 = q0 + wid * 16 + r, row1 = row0 + 8;
    float mx0 = -1e30f, mx1 = -1e30f, l0 = 0.f, l1 = 0.f;
    float oa[8][4];
    #pragma unroll
    for (int j = 0; j < 8; j++)
        #pragma unroll
        for (int t = 0; t < 4; t++) oa[j][t] = 0.f;

    int kend = (q0 < SV) ? SV : (q0 + 64);
    for (int kb = 0; kb < kend; kb += 64) {
        __syncthreads();
        #pragma unroll
        for (int i = 0; i < 16; i++) {
            int idx = tid + i * 128;
            const float* src;
            uint32_t *dh_, *dm_;
            int row, c4;
            if (idx < 1024) {
                row = idx >> 4; c4 = idx & 15;
                src = K + (size_t)(kb + row) * D_MODEL + h * DH + c4 * 4;
                dh_ = sKh; dm_ = sKm;
            } else {
                int jj = idx - 1024;
                row = jj >> 4; c4 = jj & 15;
                src = Vt + (size_t)(h * DH + row) * S_TOT + kb + c4 * 4;
                dh_ = sVh; dm_ = sVm;
            }
            float4 f = *(const float4*)src;
            uint32_t h01 = pack_bf2(f.x, f.y), h23 = pack_bf2(f.z, f.w);
            __nv_bfloat162* H01 = (__nv_bfloat162*)&h01;
            __nv_bfloat162* H23 = (__nv_bfloat162*)&h23;
            uint32_t m01 = pack_bf2(f.x - __bfloat162float(H01->x), f.y - __bfloat162float(H01->y));
            uint32_t m23 = pack_bf2(f.z - __bfloat162float(H23->x), f.w - __bfloat162float(H23->y));
            int o2 = row * FST + c4 * 2;
            dh_[o2] = h01; dh_[o2 + 1] = h23;
            dm_[o2] = m01; dm_[o2 + 1] = m23;
        }
        __syncthreads();

        // S = Q K^T
        float s[8][4];
        #pragma unroll
        for (int j = 0; j < 8; j++)
            #pragma unroll
            for (int t = 0; t < 4; t++) s[j][t] = 0.f;
        #pragma unroll
        for (int k16 = 0; k16 < 4; k16++) {
            int kw = k16 * 8;
            uint32_t ah[4], am[4];
            int mrow = wid * 16 + r;
            const uint32_t* ph = sQh + mrow * FST + kw + cq;
            ah[0] = ph[0]; ah[1] = ph[8 * FST]; ah[2] = ph[4]; ah[3] = ph[8 * FST + 4];
            const uint32_t* pm = sQm + mrow * FST + kw + cq;
            am[0] = pm[0]; am[1] = pm[8 * FST]; am[2] = pm[4]; am[3] = pm[8 * FST + 4];
            #pragma unroll
            for (int j = 0; j < 8; j++) {
                uint32_t bh[2], bm[2];
                const uint32_t* qh = sKh + (j * 8 + r) * FST + kw + cq;
                bh[0] = qh[0]; bh[1] = qh[4];
                const uint32_t* qm = sKm + (j * 8 + r) * FST + kw + cq;
                bm[0] = qm[0]; bm[1] = qm[4];
                mma16(s[j], ah, bh);
                mma16(s[j], am, bh);
                mma16(s[j], ah, bm);
            }
        }
        // structural mask (only action-key tiles)
        if (kb >= SV) {
            #pragma unroll
            for (int j = 0; j < 8; j++) {
                int key = kb + j * 8 + 2 * cq;
                if (key > row0) s[j][0] = -1e30f;
                if (key + 1 > row0) s[j][1] = -1e30f;
                if (key > row1) s[j][2] = -1e30f;
                if (key + 1 > row1) s[j][3] = -1e30f;
            }
        }
        // online softmax
        float tm0 = -1e30f, tm1 = -1e30f;
        #pragma unroll
        for (int j = 0; j < 8; j++) {
            tm0 = fmaxf(tm0, fmaxf(s[j][0], s[j][1]));
            tm1 = fmaxf(tm1, fmaxf(s[j][2], s[j][3]));
        }
        tm0 = fmaxf(tm0, __shfl_xor_sync(~0u, tm0, 1));
        tm0 = fmaxf(tm0, __shfl_xor_sync(~0u, tm0, 2));
        tm1 = fmaxf(tm1, __shfl_xor_sync(~0u, tm1, 1));
        tm1 = fmaxf(tm1, __shfl_xor_sync(~0u, tm1, 2));
        float mn0 = fmaxf(mx0, tm0), mn1 = fmaxf(mx1, tm1);
        float corr0 = fexp2((mx0 - mn0) * LOG2E);
        float corr1 = fexp2((mx1 - mn1) * LOG2E);
        mx0 = mn0; mx1 = mn1;
        float ps0 = 0.f, ps1 = 0.f;
        #pragma unroll
        for (int j = 0; j < 8; j++) {
            s[j][0] = fexp2((s[j][0] - mn0) * LOG2E);
            s[j][1] = fexp2((s[j][1] - mn0) * LOG2E);
            s[j][2] = fexp2((s[j][2] - mn1) * LOG2E);
            s[j][3] = fexp2((s[j][3] - mn1) * LOG2E);
            ps0 += s[j][0] + s[j][1];
            ps1 += s[j][2] + s[j][3];
        }
        ps0 += __shfl_xor_sync(~0u, ps0, 1); ps0 += __shfl_xor_sync(~0u, ps0, 2);
        ps1 += __shfl_xor_sync(~0u, ps1, 1); ps1 += __shfl_xor_sync(~0u, ps1, 2);
        l0 = l0 * corr0 + ps0;
        l1 = l1 * corr1 + ps1;
        #pragma unroll
        for (int j = 0; j < 8; j++) {
            oa[j][0] *= corr0; oa[j][1] *= corr0;
            oa[j][2] *= corr1; oa[j][3] *= corr1;
        }
        // O += P V  (P via C->A fragment identity)
        #pragma unroll
        for (int j2 = 0; j2 < 4; j2++) {
            int t0 = 2 * j2, t1 = 2 * j2 + 1;
            uint32_t pah[4], pam[4];
            pah[0] = pack_bf2(s[t0][0], s[t0][1]);
            pah[1] = pack_bf2(s[t0][2], s[t0][3]);
            pah[2] = pack_bf2(s[t1][0], s[t1][1]);
            pah[3] = pack_bf2(s[t1][2], s[t1][3]);
            {
                __nv_bfloat162* B0 = (__nv_bfloat162*)&pah[0];
                __nv_bfloat162* B1 = (__nv_bfloat162*)&pah[1];
                __nv_bfloat162* B2 = (__nv_bfloat162*)&pah[2];
                __nv_bfloat162* B3 = (__nv_bfloat162*)&pah[3];
                pam[0] = pack_bf2(s[t0][0] - __bfloat162float(B0->x), s[t0][1] - __bfloat162float(B0->y));
                pam[1] = pack_bf2(s[t0][2] - __bfloat162float(B1->x), s[t0][3] - __bfloat162float(B1->y));
                pam[2] = pack_bf2(s[t1][0] - __bfloat162float(B2->x), s[t1][1] - __bfloat162float(B2->y));
                pam[3] = pack_bf2(s[t1][2] - __bfloat162float(B3->x), s[t1][3] - __bfloat162float(B3->y));
            }
            int kw = j2 * 8;
            #pragma unroll
            for (int jn = 0; jn < 8; jn++) {
                uint32_t bh[2], bm[2];
                const uint32_t* qh = sVh + (jn * 8 + r) * FST + kw + cq;
                bh[0] = qh[0]; bh[1] = qh[4];
                const uint32_t* qm = sVm + (jn * 8 + r) * FST + kw + cq;
                bm[0] = qm[0]; bm[1] = qm[4];
                mma16(oa[jn], pah, bh);
                mma16(oa[jn], pam, bh);
                mma16(oa[jn], pah, bm);
            }
        }
    }

    float inv0 = 1.f / l0, inv1 = 1.f / l1;
    #pragma unroll
    for (int jn = 0; jn < 8; jn++) {
        int col = h * DH + jn * 8 + cq * 2;
        float2 o0; o0.x = oa[jn][0] * inv0; o0.y = oa[jn][1] * inv0;
        float2 o1; o1.x = oa[jn][2] * inv1; o1.y = oa[jn][3] * inv1;
        *(float2*)(O + (size_t)row0 * D_MODEL + col) = o0;
        *(float2*)(O + (size_t)row1 * D_MODEL + col) = o1;
    }
}

// ---------- mma.sync 3-term BF16-split GEMM ----------
template <int BN, int EPI>
__global__ void __launch_bounds__((BN == 128) ? 256 : 128) tgemm(
    const float* __restrict__ A, const float* __restrict__ Bt,
    const float* __restrict__ bias, float* __restrict__ C,
    const float* __restrict__ res, const float* __restrict__ gate,
    int K, int lda, int ldb, int ldc) {
    constexpr int THREADS = (BN == 128) ? 256 : 128;
    constexpr int NF4 = (128 + BN) * 8;
    constexpr int NPF = NF4 / THREADS;
    constexpr int AHI = 0, AMI = 2560, BHIo = 5120, BMIo = 5120 + BN * 20;
    constexpr int STG = 5120 + BN * 40;
    constexpr int WX = BN / 32;

    extern __shared__ uint32_t smw[];
    int tid = threadIdx.x;
    int wid = tid >> 5, lane = tid & 31;
    int wy = wid / WX, wx = wid % WX;
    int r = lane >> 2, cq = lane & 3;

    A += (size_t)blockIdx.y * 128 * lda;
    Bt += (size_t)blockIdx.x * BN * ldb;

    float acc[4][4][4];
    #pragma unroll
    for (int i = 0; i < 4; i++)
        #pragma unroll
        for (int j = 0; j < 4; j++)
            #pragma unroll
            for (int t = 0; t < 4; t++) acc[i][j][t] = 0.f;

    float4 pf[NPF];

    auto loadG = [&](int c) {
        #pragma unroll
        for (int t = 0; t < NPF; t++) {
            int idx = tid + t * THREADS;
            const float* src;
            if (idx < 1024) src = A + (size_t)(idx >> 3) * lda + c * 32 + (idx & 7) * 4;
            else { int bi = idx - 1024; src = Bt + (size_t)(bi >> 3) * ldb + c * 32 + (bi & 7) * 4; }
            pf[t] = *(const float4*)src;
        }
    };
    auto storeS = [&](int s) {
        uint32_t* base = smw + s * STG;
        #pragma unroll
        for (int t = 0; t < NPF; t++) {
            float4 f = pf[t];
            uint32_t h01 = pack_bf2(f.x, f.y), h23 = pack_bf2(f.z, f.w);
            __nv_bfloat162* H01 = (__nv_bfloat162*)&h01;
            __nv_bfloat162* H23 = (__nv_bfloat162*)&h23;
            uint32_t m01 = pack_bf2(f.x - __bfloat162float(H01->x), f.y - __bfloat162float(H01->y));
            uint32_t m23 = pack_bf2(f.z - __bfloat162float(H23->x), f.w - __bfloat162float(H23->y));
            int idx = tid + t * THREADS;
            uint32_t* dst;
            int mo;
            if (idx < 1024) { dst = base + AHI + (idx >> 3) * 20 + (idx & 7) * 2; mo = AMI - AHI; }
            else { int bi = idx - 1024; dst = base + BHIo + (bi >> 3) * 20 + (bi & 7) * 2; mo = BMIo - BHIo; }
            dst[0] = h01; dst[1] = h23;
            dst[mo] = m01; dst[mo + 1] = m23;
        }
    };
    auto compute = [&](int s) {
        const uint32_t* base = smw + s * STG;
        #pragma unroll
        for (int k16 = 0; k16 < 2; k16++) {
            int kw = k16 * 8;
            uint32_t ah[4][4], am[4][4], bh[4][2], bm[4][2];
            #pragma unroll
            for (int i = 0; i < 4; i++) {
                int mrow = wy * 64 + i * 16 + r;
                const uint32_t* ph = base + AHI + mrow * 20 + kw + cq;
                ah[i][0] = ph[0]; ah[i][1] = ph[8 * 20]; ah[i][2] = ph[4]; ah[i][3] = ph[8 * 20 + 4];
                const uint32_t* pm = base + AMI + mrow * 20 + kw + cq;
                am[i][0] = pm[0]; am[i][1] = pm[8 * 20]; am[i][2] = pm[4]; am[i][3] = pm[8 * 20 + 4];
            }
            #pragma unroll
            for (int j = 0; j < 4; j++) {
                int nrow = wx * 32 + j * 8 + r;
                const uint32_t* ph = base + BHIo + nrow * 20 + kw + cq;
                bh[j][0] = ph[0]; bh[j][1] = ph[4];
                const uint32_t* pm = base + BMIo + nrow * 20 + kw + cq;
                bm[j][0] = pm[0]; bm[j][1] = pm[4];
            }
            #pragma unroll
            for (int i = 0; i < 4; i++)
                #pragma unroll
                for (int j = 0; j < 4; j++) {
                    mma16(acc[i][j], ah[i], bh[j]);
                    mma16(acc[i][j], am[i], bh[j]);
                    mma16(acc[i][j], ah[i], bm[j]);
                }
        }
    };

    loadG(0);
    storeS(0);
    __syncthreads();
    int NC = K >> 5;
    for (int c = 0; c < NC; c++) {
        if (c + 1 < NC) loadG(c + 1);
        compute(c & 1);
        if (c + 1 < NC) storeS((c + 1) & 1);
        __syncthreads();
    }

    int rowb = blockIdx.y * 128 + wy * 64;
    int colb = blockIdx.x * BN + wx * 32;
    #pragma unroll
    for (int i = 0; i < 4; i++) {
        #pragma unroll
        for (int j = 0; j < 4; j++) {
            int col = colb + j * 8 + cq * 2;
            #pragma unroll
            for (int h = 0; h < 2; h++) {
                int row = rowb + i * 16 + r + h * 8;
                float v0 = acc[i][j][h * 2], v1 = acc[i][j][h * 2 + 1];
                v0 += bias[col]; v1 += bias[col + 1];
                if (EPI == 1) {
                    float t0 = v0, t1 = v1;
                    v0 = 0.5f * t0 * (1.f + tanhf(0.7978845608028654f * (t0 + 0.044715f * t0 * t0 * t0)));
                    v1 = 0.5f * t1 * (1.f + tanhf(0.7978845608028654f * (t1 + 0.044715f * t1 * t1 * t1)));
                } else if (EPI == 2) {
                    float2 rv = *(const float2*)(res + (size_t)row * ldc + col);
                    v0 = rv.x + gate[col] * v0;
                    v1 = rv.y + gate[col + 1] * v1;
                }
                float2 ov; ov.x = v0; ov.y = v1;
                *(float2*)(C + (size_t)row * ldc + col) = ov;
            }
        }
    }
}

extern "C" void kernel_launch(void* const* d_in, const int* in_sizes, int n_in,
                              void* d_out, int out_size) {
    const float* video = (const float*)d_in[0];
    const float* action = (const float*)d_in[1];
    const float* vfreq = (const float*)d_in[2];
    const float* afreq = (const float*)d_in[3];
    const float* vtmod = (const float*)d_in[4];
    const float* atmod = (const float*)d_in[5];
    const float* Wq = (const float*)d_in[6];
    const float* Wk = (const float*)d_in[7];
    const float* Wv = (const float*)d_in[8];
    const float* Wo = (const float*)d_in[9];
    const float* bq = (const float*)d_in[10];
    const float* bk = (const float*)d_in[11];
    const float* bv = (const float*)d_in[12];
    const float* bo = (const float*)d_in[13];
    const float* gq = (const float*)d_in[14];
    const float* gk = (const float*)d_in[15];
    const float* mod = (const float*)d_in[16];
    const float* W1 = (const float*)d_in[17];
    const float* b1 = (const float*)d_in[18];
    const float* W2 = (const float*)d_in[19];
    const float* b2 = (const float*)d_in[20];
    float* out = (float*)d_out;

    float *x, *a, *q, *k, *v, *vt, *o, *hbuf, *m6;
    float *wqt, *wkt, *wvt, *wot, *w1t, *w2t;
    cudaGetSymbolAddress((void**)&x, g_x);
    cudaGetSymbolAddress((void**)&a, g_a);
    cudaGetSymbolAddress((void**)&q, g_q);
    cudaGetSymbolAddress((void**)&k, g_k);
    cudaGetSymbolAddress((void**)&v, g_v);
    cudaGetSymbolAddress((void**)&vt, g_vt);
    cudaGetSymbolAddress((void**)&o, g_o);
    cudaGetSymbolAddress((void**)&hbuf, g_h);
    cudaGetSymbolAddress((void**)&m6, g_m6);
    cudaGetSymbolAddress((void**)&wqt, g_wqt);
    cudaGetSymbolAddress((void**)&wkt, g_wkt);
    cudaGetSymbolAddress((void**)&wvt, g_wvt);
    cudaGetSymbolAddress((void**)&wot, g_wot);
    cudaGetSymbolAddress((void**)&w1t, g_w1t);
    cudaGetSymbolAddress((void**)&w2t, g_w2t);

    const int SM128 = (5120 + 128 * 40) * 2 * 4;
    cudaFuncSetAttribute(tgemm<128, 0>, cudaFuncAttributeMaxDynamicSharedMemorySize, SM128);
    cudaFuncSetAttribute(tgemm<128, 1>, cudaFuncAttributeMaxDynamicSharedMemorySize, SM128);
    cudaFuncSetAttribute(tgemm<128, 2>, cudaFuncAttributeMaxDynamicSharedMemorySize, SM128);

    dim3 tb(32, 8);
    for (int e = 0; e < 2; e++)
        for (int l = 0; l < NL; l++) {
            size_t off = (size_t)(e * NL + l) * D_MODEL * D_MODEL;
            dim3 gdd(D_MODEL / 32, D_MODEL / 32);
            transpose_kernel<<<gdd, tb>>>(Wq + off, wqt + off, D_MODEL, D_MODEL);
            transpose_kernel<<<gdd, tb>>>(Wk + off, wkt + off, D_MODEL, D_MODEL);
            transpose_kernel<<<gdd, tb>>>(Wv + off, wvt + off, D_MODEL, D_MODEL);
            transpose_kernel<<<gdd, tb>>>(Wo + off, wot + off, D_MODEL, D_MODEL);
            size_t off1 = (size_t)(e * NL + l) * D_MODEL * FF;
            transpose_kernel<<<dim3(FF / 32, D_MODEL / 32), tb>>>(W1 + off1, w1t + off1, D_MODEL, FF);
            transpose_kernel<<<dim3(D_MODEL / 32, FF / 32), tb>>>(W2 + off1, w2t + off1, FF, D_MODEL);
        }

    cudaMemcpyAsync(x, video, (size_t)SV * D_MODEL * 4, cudaMemcpyDeviceToDevice);
    cudaMemcpyAsync(x + (size_t)SV * D_MODEL, action, (size_t)SA * D_MODEL * 4, cudaMemcpyDeviceToDevice);

    for (int l = 0; l < NL; l++) {
        m6_kernel<<<48, 256>>>(mod, vtmod, atmod, m6, l);
        lnmod_kernel<<<S_TOT, 256>>>(x, a, m6, 0, 1);

        for (int e = 0; e < 2; e++) {
            int M = e ? SA : SV;
            size_t roff = e ? (size_t)SV * D_MODEL : 0;
            size_t woff = (size_t)(e * NL + l) * D_MODEL * D_MODEL;
            size_t boff = (size_t)(e * NL + l) * D_MODEL;
            dim3 g(D_MODEL / 128, M / 128);
            tgemm<128, 0><<<g, 256, SM128>>>(a + roff, wqt + woff, bq + boff, q + roff,
                nullptr, nullptr, D_MODEL, D_MODEL, D_MODEL, D_MODEL);
            tgemm<128, 0><<<g, 256, SM128>>>(a + roff, wkt + woff, bk + boff, k + roff,
                nullptr, nullptr, D_MODEL, D_MODEL, D_MODEL, D_MODEL);
            tgemm<128, 0><<<g, 256, SM128>>>(a + roff, wvt + woff, bv + boff, v + roff,
                nullptr, nullptr, D_MODEL, D_MODEL, D_MODEL, D_MODEL);
        }
        rmsrope_kernel<<<S_TOT, 256>>>(q, gq, vfreq, afreq, l);
        rmsrope_kernel<<<S_TOT, 256>>>(k, gk, vfreq, afreq, l);

        transpose_kernel<<<dim3(D_MODEL / 32, S_TOT / 32), tb>>>(v, vt, S_TOT, D_MODEL);
        flash_kernel<<<dim3(NH, S_TOT / 64), 128>>>(q, k, vt, o);

        for (int e = 0; e < 2; e++) {
            int M = e ? SA : SV;
            size_t roff = e ? (size_t)SV * D_MODEL : 0;
            size_t woff = (size_t)(e * NL + l) * D_MODEL * D_MODEL;
            size_t boff = (size_t)(e * NL + l) * D_MODEL;
            dim3 g(D_MODEL / 128, M / 128);
            tgemm<128, 2><<<g, 256, SM128>>>(o + roff, wot + woff, bo + boff, x + roff,
                x + roff, m6 + (size_t)(e * 6 + 2) * D_MODEL,
                D_MODEL, D_MODEL, D_MODEL, D_MODEL);
        }

        lnmod_kernel<<<S_TOT, 256>>>(x, a, m6, 3, 4);

        for (int e = 0; e < 2; e++) {
            int M = e ? SA : SV;
            size_t roff = e ? (size_t)SV * D_MODEL : 0;
            size_t hoff = e ? (size_t)SV * FF : 0;
            size_t w1off = (size_t)(e * NL + l) * D_MODEL * FF;
            size_t b1off = (size_t)(e * NL + l) * FF;
            size_t b2off = (size_t)(e * NL + l) * D_MODEL;
            tgemm<128, 1><<<dim3(FF / 128, M / 128), 256, SM128>>>(
                a + roff, w1t + w1off, b1 + b1off, hbuf + hoff,
                nullptr, nullptr, D_MODEL, D_MODEL, D_MODEL, FF);
            tgemm<128, 2><<<dim3(D_MODEL / 128, M / 128), 256, SM128>>>(
                hbuf + hoff, w2t + w1off, b2 + b2off, x + roff,
                x + roff, m6 + (size_t)(e * 6 + 5) * D_MODEL,
                FF, FF, FF, D_MODEL);
        }
    }

    cudaMemcpyAsync(out, x, (size_t)S_TOT * D_MODEL * 4, cudaMemcpyDeviceToDevice);
}

// round 8
// speedup vs baseline: 4.6978x; 1.0659x over previous
#include <cuda_runtime.h>
#include <cuda_bf16.h>
#include <math.h>
#include <stdint.h>

#define SV 2048
#define SA 512
#define S_TOT 2560
#define D_MODEL 1024
#define NH 16
#define DH 64
#define FF 4096
#define NL 2
#define LOG2E 1.4426950408889634f

__device__ float g_x[S_TOT * D_MODEL];
__device__ float g_a[S_TOT * D_MODEL];
__device__ float g_q[S_TOT * D_MODEL];
__device__ float g_k[S_TOT * D_MODEL];
__device__ float g_v[S_TOT * D_MODEL];
__device__ float g_vt[D_MODEL * S_TOT];
__device__ float g_o[S_TOT * D_MODEL];
__device__ float g_h[S_TOT * FF];
__device__ float g_m6[2 * 6 * D_MODEL];
__device__ float g_wqt[NL * 2 * D_MODEL * D_MODEL];
__device__ float g_wkt[NL * 2 * D_MODEL * D_MODEL];
__device__ float g_wvt[NL * 2 * D_MODEL * D_MODEL];
__device__ float g_wot[NL * 2 * D_MODEL * D_MODEL];
__device__ float g_w1t[(size_t)NL * 2 * D_MODEL * FF];
__device__ float g_w2t[(size_t)NL * 2 * FF * D_MODEL];

struct GemmArgs {
    const float* A;
    const float* Bt[3];
    const float* bias[3];
    float* C[3];
    const float* res;
    const float* m6;
    int gidx;
    int K, lda, ldb, ldc;
    size_t westride, bestride;
};

__device__ __forceinline__ void mma16(float* d, const uint32_t* a, const uint32_t* b) {
    asm volatile("mma.sync.aligned.m16n8k16.row.col.f32.bf16.bf16.f32 "
        "{%0,%1,%2,%3}, {%4,%5,%6,%7}, {%8,%9}, {%0,%1,%2,%3};"
        : "+f"(d[0]), "+f"(d[1]), "+f"(d[2]), "+f"(d[3])
        : "r"(a[0]), "r"(a[1]), "r"(a[2]), "r"(a[3]), "r"(b[0]), "r"(b[1]));
}

// fast 2^x for x <= 0, FMA-pipe only
__device__ __forceinline__ float fexp2(float x) {
    x = fmaxf(x, -126.f);
    float fl = floorf(x);
    float f = x - fl;
    float p = 1.54035304e-4f;
    p = fmaf(p, f, 1.33335581e-3f);
    p = fmaf(p, f, 9.61812911e-3f);
    p = fmaf(p, f, 5.55041087e-2f);
    p = fmaf(p, f, 2.40226507e-1f);
    p = fmaf(p, f, 6.93147181e-1f);
    p = fmaf(p, f, 1.0f);
    return p * __int_as_float(((int)fl + 127) << 23);
}

__device__ __forceinline__ uint32_t pack_bf2(float a, float b) {
    __nv_bfloat162 t = __floats2bfloat162_rn(a, b);
    return *(const uint32_t*)&t;
}

__device__ __forceinline__ void blockReduce2(float& s, float& ss) {
    __shared__ float bufs[8], bufss[8];
    #pragma unroll
    for (int o = 16; o; o >>= 1) {
        s += __shfl_xor_sync(~0u, s, o); ss += __shfl_xor_sync(~0u, ss, o);
    }
    int w = threadIdx.x >> 5;
    if ((threadIdx.x & 31) == 0) { bufs[w] = s; bufss[w] = ss; }
    __syncthreads();
    if (threadIdx.x < 32) {
        s = (threadIdx.x < 8) ? bufs[threadIdx.x] : 0.f;
        ss = (threadIdx.x < 8) ? bufss[threadIdx.x] : 0.f;
        #pragma unroll
        for (int o = 4; o; o >>= 1) {
            s += __shfl_xor_sync(~0u, s, o); ss += __shfl_xor_sync(~0u, ss, o);
        }
        if (threadIdx.x == 0) { bufs[0] = s; bufss[0] = ss; }
    }
    __syncthreads();
    s = bufs[0]; ss = bufss[0];
}

__global__ void m6_kernel(const float* __restrict__ mod, const float* __restrict__ vt,
                          const float* __restrict__ at, float* __restrict__ m6, int l) {
    int idx = blockIdx.x * blockDim.x + threadIdx.x;
    if (idx >= 2 * 6 * D_MODEL) return;
    int e = idx / (6 * D_MODEL);
    int rem = idx % (6 * D_MODEL);
    m6[idx] = mod[((size_t)(e * NL + l) * 6) * D_MODEL + rem] + (e ? at[rem] : vt[rem]);
}

__global__ void __launch_bounds__(256) lnmod_kernel(const float* __restrict__ x, float* __restrict__ a,
                                                    const float* __restrict__ m6, int jsh, int jsc) {
    int row = blockIdx.x;
    int e = (row >= SV) ? 1 : 0;
    const float4* shv4 = (const float4*)(m6 + (size_t)(e * 6 + jsh) * D_MODEL);
    const float4* scv4 = (const float4*)(m6 + (size_t)(e * 6 + jsc) * D_MODEL);
    float4 v = ((const float4*)(x + (size_t)row * D_MODEL))[threadIdx.x];
    float s = v.x + v.y + v.z + v.w;
    float ss = v.x * v.x + v.y * v.y + v.z * v.z + v.w * v.w;
    blockReduce2(s, ss);
    float mu = s * (1.f / D_MODEL);
    float var = ss * (1.f / D_MODEL) - mu * mu;
    float r = rsqrtf(var + 1e-6f);
    float4 sh = shv4[threadIdx.x], sc = scv4[threadIdx.x];
    float4 o;
    o.x = (v.x - mu) * r * (1.f + sc.x) + sh.x;
    o.y = (v.y - mu) * r * (1.f + sc.y) + sh.y;
    o.z = (v.z - mu) * r * (1.f + sc.z) + sh.z;
    o.w = (v.w - mu) * r * (1.f + sc.w) + sh.w;
    ((float4*)(a + (size_t)row * D_MODEL))[threadIdx.x] = o;
}

// merged rmsnorm+rope for q (blocks [0,S_TOT)) and k (blocks [S_TOT, 2*S_TOT))
__global__ void __launch_bounds__(256) rmsrope_kernel(float* __restrict__ qb, float* __restrict__ kb,
                                                      const float* __restrict__ gq, const float* __restrict__ gk,
                                                      const float* __restrict__ vfreq, const float* __restrict__ afreq,
                                                      int l) {
    int bid = blockIdx.x;
    int isk = (bid >= S_TOT);
    int row = isk ? bid - S_TOT : bid;
    float* q = isk ? kb : qb;
    const float* gbase = isk ? gk : gq;
    int e = (row >= SV) ? 1 : 0;
    int pos = e ? row - SV : row;
    const float* fr = e ? (afreq + (size_t)pos * (DH / 2)) : (vfreq + (size_t)pos * (DH / 2));
    const float* g = gbase + (size_t)(e * NL + l) * D_MODEL;
    float4 v = ((const float4*)(q + (size_t)row * D_MODEL))[threadIdx.x];
    float ss = v.x * v.x + v.y * v.y + v.z * v.z + v.w * v.w, dummy = 0.f;
    blockReduce2(ss, dummy);
    float r = rsqrtf(ss * (1.f / D_MODEL) + 1e-6f);
    float4 gv = ((const float4*)g)[threadIdx.x];
    int d0 = threadIdx.x * 4;
    int j0 = (d0 & (DH - 1)) >> 1, j1 = j0 + 1;
    float c0 = cosf(fr[j0]), s0 = sinf(fr[j0]);
    float c1 = cosf(fr[j1]), s1 = sinf(fr[j1]);
    float xe0 = v.x * r * gv.x, xo0 = v.y * r * gv.y;
    float xe1 = v.z * r * gv.z, xo1 = v.w * r * gv.w;
    float4 o;
    o.x = xe0 * c0 - xo0 * s0; o.y = xe0 * s0 + xo0 * c0;
    o.z = xe1 * c1 - xo1 * s1; o.w = xe1 * s1 + xo1 * c1;
    ((float4*)(q + (size_t)row * D_MODEL))[threadIdx.x] = o;
}

// batched transpose: z selects matrix (src + z*msize -> dst + z*msize), each [R,C] -> [C,R]
__global__ void __launch_bounds__(256) transpose_kernel(const float* __restrict__ src, float* __restrict__ dst,
                                                        int R, int C, size_t msize) {
    __shared__ float t[32][33];
    src += blockIdx.z * msize;
    dst += blockIdx.z * msize;
    int bx = blockIdx.x * 32, by = blockIdx.y * 32;
    for (int i = threadIdx.y; i < 32; i += 8)
        t[i][threadIdx.x] = src[(size_t)(by + i) * C + bx + threadIdx.x];
    __syncthreads();
    for (int i = threadIdx.y; i < 32; i += 8)
        dst[(size_t)(bx + i) * R + by + threadIdx.x] = t[threadIdx.x][i];
}

// ---------------- flash attention (bf16 3-term, online softmax) ----------------
#define FST 36
__global__ void __launch_bounds__(128) flash_kernel(
    const float* __restrict__ Q, const float* __restrict__ K,
    const float* __restrict__ Vt, float* __restrict__ O) {
    __shared__ uint32_t sQh[64 * FST], sQm[64 * FST], sKh[64 * FST], sKm[64 * FST],
                        sVh[64 * FST], sVm[64 * FST];
    int h = blockIdx.x;
    int q0 = blockIdx.y * 64;
    int tid = threadIdx.x, wid = tid >> 5, lane = tid & 31;
    int r = lane >> 2, cq = lane & 3;

    #pragma unroll
    for (int i = 0; i < 8; i++) {
        int idx = tid + i * 128;
        int row = idx >> 4, c4 = idx & 15;
        float4 f = *(const float4*)(Q + (size_t)(q0 + row) * D_MODEL + h * DH + c4 * 4);
        f.x *= 0.125f; f.y *= 0.125f; f.z *= 0.125f; f.w *= 0.125f;
        uint32_t h01 = pack_bf2(f.x, f.y), h23 = pack_bf2(f.z, f.w);
        __nv_bfloat162* H01 = (__nv_bfloat162*)&h01;
        __nv_bfloat162* H23 = (__nv_bfloat162*)&h23;
        uint32_t m01 = pack_bf2(f.x - __bfloat162float(H01->x), f.y - __bfloat162float(H01->y));
        uint32_t m23 = pack_bf2(f.z - __bfloat162float(H23->x), f.w - __bfloat162float(H23->y));
        int o2 = row * FST + c4 * 2;
        sQh[o2] = h01; sQh[o2 + 1] = h23;
        sQm[o2] = m01; sQm[o2 + 1] = m23;
    }

    int row0 = q0 + wid * 16 + r, row1 = row0 + 8;
    float mx0 = -1e30f, mx1 = -1e30f, l0 = 0.f, l1 = 0.f;
    float oa[8][4];
    #pragma unroll
    for (int j = 0; j < 8; j++)
        #pragma unroll
        for (int t = 0; t < 4; t++) oa[j][t] = 0.f;

    int kend = (q0 < SV) ? SV : (q0 + 64);
    for (int kb = 0; kb < kend; kb += 64) {
        __syncthreads();
        #pragma unroll
        for (int i = 0; i < 16; i++) {
            int idx = tid + i * 128;
            const float* src;
            uint32_t *dh_, *dm_;
            int row, c4;
            if (idx < 1024) {
                row = idx >> 4; c4 = idx & 15;
                src = K + (size_t)(kb + row) * D_MODEL + h * DH + c4 * 4;
                dh_ = sKh; dm_ = sKm;
            } else {
                int jj = idx - 1024;
                row = jj >> 4; c4 = jj & 15;
                src = Vt + (size_t)(h * DH + row) * S_TOT + kb + c4 * 4;
                dh_ = sVh; dm_ = sVm;
            }
            float4 f = *(const float4*)src;
            uint32_t h01 = pack_bf2(f.x, f.y), h23 = pack_bf2(f.z, f.w);
            __nv_bfloat162* H01 = (__nv_bfloat162*)&h01;
            __nv_bfloat162* H23 = (__nv_bfloat162*)&h23;
            uint32_t m01 = pack_bf2(f.x - __bfloat162float(H01->x), f.y - __bfloat162float(H01->y));
            uint32_t m23 = pack_bf2(f.z - __bfloat162float(H23->x), f.w - __bfloat162float(H23->y));
            int o2 = row * FST + c4 * 2;
            dh_[o2] = h01; dh_[o2 + 1] = h23;
            dm_[o2] = m01; dm_[o2 + 1] = m23;
        }
        __syncthreads();

        float s[8][4];
        #pragma unroll
        for (int j = 0; j < 8; j++)
            #pragma unroll
            for (int t = 0; t < 4; t++) s[j][t] = 0.f;
        #pragma unroll
        for (int k16 = 0; k16 < 4; k16++) {
            int kw = k16 * 8;
            uint32_t ah[4], am[4];
            int mrow = wid * 16 + r;
            const uint32_t* ph = sQh + mrow * FST + kw + cq;
            ah[0] = ph[0]; ah[1] = ph[8 * FST]; ah[2] = ph[4]; ah[3] = ph[8 * FST + 4];
            const uint32_t* pm = sQm + mrow * FST + kw + cq;
            am[0] = pm[0]; am[1] = pm[8 * FST]; am[2] = pm[4]; am[3] = pm[8 * FST + 4];
            #pragma unroll
            for (int j = 0; j < 8; j++) {
                uint32_t bh[2], bm[2];
                const uint32_t* qh = sKh + (j * 8 + r) * FST + kw + cq;
                bh[0] = qh[0]; bh[1] = qh[4];
                const uint32_t* qm = sKm + (j * 8 + r) * FST + kw + cq;
                bm[0] = qm[0]; bm[1] = qm[4];
                mma16(s[j], ah, bh);
                mma16(s[j], am, bh);
                mma16(s[j], ah, bm);
            }
        }
        if (kb >= SV) {
            #pragma unroll
            for (int j = 0; j < 8; j++) {
                int key = kb + j * 8 + 2 * cq;
                if (key > row0) s[j][0] = -1e30f;
                if (key + 1 > row0) s[j][1] = -1e30f;
                if (key > row1) s[j][2] = -1e30f;
                if (key + 1 > row1) s[j][3] = -1e30f;
            }
        }
        float tm0 = -1e30f, tm1 = -1e30f;
        #pragma unroll
        for (int j = 0; j < 8; j++) {
            tm0 = fmaxf(tm0, fmaxf(s[j][0], s[j][1]));
            tm1 = fmaxf(tm1, fmaxf(s[j][2], s[j][3]));
        }
        tm0 = fmaxf(tm0, __shfl_xor_sync(~0u, tm0, 1));
        tm0 = fmaxf(tm0, __shfl_xor_sync(~0u, tm0, 2));
        tm1 = fmaxf(tm1, __shfl_xor_sync(~0u, tm1, 1));
        tm1 = fmaxf(tm1, __shfl_xor_sync(~0u, tm1, 2));
        float mn0 = fmaxf(mx0, tm0), mn1 = fmaxf(mx1, tm1);
        float corr0 = fexp2((mx0 - mn0) * LOG2E);
        float corr1 = fexp2((mx1 - mn1) * LOG2E);
        mx0 = mn0; mx1 = mn1;
        float ps0 = 0.f, ps1 = 0.f;
        #pragma unroll
        for (int j = 0; j < 8; j++) {
            s[j][0] = fexp2((s[j][0] - mn0) * LOG2E);
            s[j][1] = fexp2((s[j][1] - mn0) * LOG2E);
            s[j][2] = fexp2((s[j][2] - mn1) * LOG2E);
            s[j][3] = fexp2((s[j][3] - mn1) * LOG2E);
            ps0 += s[j][0] + s[j][1];
            ps1 += s[j][2] + s[j][3];
        }
        ps0 += __shfl_xor_sync(~0u, ps0, 1); ps0 += __shfl_xor_sync(~0u, ps0, 2);
        ps1 += __shfl_xor_sync(~0u, ps1, 1); ps1 += __shfl_xor_sync(~0u, ps1, 2);
        l0 = l0 * corr0 + ps0;
        l1 = l1 * corr1 + ps1;
        #pragma unroll
        for (int j = 0; j < 8; j++) {
            oa[j][0] *= corr0; oa[j][1] *= corr0;
            oa[j][2] *= corr1; oa[j][3] *= corr1;
        }
        #pragma unroll
        for (int j2 = 0; j2 < 4; j2++) {
            int t0 = 2 * j2, t1 = 2 * j2 + 1;
            uint32_t pah[4], pam[4];
            pah[0] = pack_bf2(s[t0][0], s[t0][1]);
            pah[1] = pack_bf2(s[t0][2], s[t0][3]);
            pah[2] = pack_bf2(s[t1][0], s[t1][1]);
            pah[3] = pack_bf2(s[t1][2], s[t1][3]);
            {
                __nv_bfloat162* B0 = (__nv_bfloat162*)&pah[0];
                __nv_bfloat162* B1 = (__nv_bfloat162*)&pah[1];
                __nv_bfloat162* B2 = (__nv_bfloat162*)&pah[2];
                __nv_bfloat162* B3 = (__nv_bfloat162*)&pah[3];
                pam[0] = pack_bf2(s[t0][0] - __bfloat162float(B0->x), s[t0][1] - __bfloat162float(B0->y));
                pam[1] = pack_bf2(s[t0][2] - __bfloat162float(B1->x), s[t0][3] - __bfloat162float(B1->y));
                pam[2] = pack_bf2(s[t1][0] - __bfloat162float(B2->x), s[t1][1] - __bfloat162float(B2->y));
                pam[3] = pack_bf2(s[t1][2] - __bfloat162float(B3->x), s[t1][3] - __bfloat162float(B3->y));
            }
            int kw = j2 * 8;
            #pragma unroll
            for (int jn = 0; jn < 8; jn++) {
                uint32_t bh[2], bm[2];
                const uint32_t* qh = sVh + (jn * 8 + r) * FST + kw + cq;
                bh[0] = qh[0]; bh[1] = qh[4];
                const uint32_t* qm = sVm + (jn * 8 + r) * FST + kw + cq;
                bm[0] = qm[0]; bm[1] = qm[4];
                mma16(oa[jn], pah, bh);
                mma16(oa[jn], pam, bh);
                mma16(oa[jn], pah, bm);
            }
        }
    }

    float inv0 = 1.f / l0, inv1 = 1.f / l1;
    #pragma unroll
    for (int jn = 0; jn < 8; jn++) {
        int col = h * DH + jn * 8 + cq * 2;
        float2 o0; o0.x = oa[jn][0] * inv0; o0.y = oa[jn][1] * inv0;
        float2 o1; o1.x = oa[jn][2] * inv1; o1.y = oa[jn][3] * inv1;
        *(float2*)(O + (size_t)row0 * D_MODEL + col) = o0;
        *(float2*)(O + (size_t)row1 * D_MODEL + col) = o1;
    }
}

// ---------- merged mma.sync 3-term BF16-split GEMM ----------
// grid: (N/BN, M/128, nZ). e selected by row tile; weight/bias offset by e-stride.
// EPI 0:+bias 1:gelu(+bias) 2:res+gate*(+bias), gate = m6[(e*6+gidx)*D + col]
template <int BN, int EPI>
__global__ void __launch_bounds__((BN == 128) ? 256 : 128) tgemm(GemmArgs args) {
    constexpr int THREADS = (BN == 128) ? 256 : 128;
    constexpr int NF4 = (128 + BN) * 8;
    constexpr int NPF = NF4 / THREADS;
    constexpr int AHI = 0, AMI = 2560, BHIo = 5120, BMIo = 5120 + BN * 20;
    constexpr int STG = 5120 + BN * 40;
    constexpr int WX = BN / 32;

    extern __shared__ uint32_t smw[];
    int tid = threadIdx.x;
    int wid = tid >> 5, lane = tid & 31;
    int wy = wid / WX, wx = wid % WX;
    int r = lane >> 2, cq = lane & 3;
    int z = blockIdx.z;
    int e = (blockIdx.y * 128 >= SV) ? 1 : 0;

    int lda = args.lda, ldb = args.ldb, ldc = args.ldc;
    const float* A = args.A + (size_t)blockIdx.y * 128 * lda;
    const float* Bt = args.Bt[z] + (size_t)e * args.westride + (size_t)blockIdx.x * BN * ldb;
    const float* bias = args.bias[z] + (size_t)e * args.bestride;
    float* C = args.C[z];
    const float* gate = (EPI == 2) ? (args.m6 + (size_t)(e * 6 + args.gidx) * D_MODEL) : nullptr;
    int K = args.K;

    float acc[4][4][4];
    #pragma unroll
    for (int i = 0; i < 4; i++)
        #pragma unroll
        for (int j = 0; j < 4; j++)
            #pragma unroll
            for (int t = 0; t < 4; t++) acc[i][j][t] = 0.f;

    float4 pf[NPF];

    auto loadG = [&](int c) {
        #pragma unroll
        for (int t = 0; t < NPF; t++) {
            int idx = tid + t * THREADS;
            const float* src;
            if (idx < 1024) src = A + (size_t)(idx >> 3) * lda + c * 32 + (idx & 7) * 4;
            else { int bi = idx - 1024; src = Bt + (size_t)(bi >> 3) * ldb + c * 32 + (bi & 7) * 4; }
            pf[t] = *(const float4*)src;
        }
    };
    auto storeS = [&](int s) {
        uint32_t* base = smw + s * STG;
        #pragma unroll
        for (int t = 0; t < NPF; t++) {
            float4 f = pf[t];
            uint32_t h01 = pack_bf2(f.x, f.y), h23 = pack_bf2(f.z, f.w);
            __nv_bfloat162* H01 = (__nv_bfloat162*)&h01;
            __nv_bfloat162* H23 = (__nv_bfloat162*)&h23;
            uint32_t m01 = pack_bf2(f.x - __bfloat162float(H01->x), f.y - __bfloat162float(H01->y));
            uint32_t m23 = pack_bf2(f.z - __bfloat162float(H23->x), f.w - __bfloat162float(H23->y));
            int idx = tid + t * THREADS;
            uint32_t* dst;
            int mo;
            if (idx < 1024) { dst = base + AHI + (idx >> 3) * 20 + (idx & 7) * 2; mo = AMI - AHI; }
            else { int bi = idx - 1024; dst = base + BHIo + (bi >> 3) * 20 + (bi & 7) * 2; mo = BMIo - BHIo; }
            dst[0] = h01; dst[1] = h23;
            dst[mo] = m01; dst[mo + 1] = m23;
        }
    };
    auto compute = [&](int s) {
        const uint32_t* base = smw + s * STG;
        #pragma unroll
        for (int k16 = 0; k16 < 2; k16++) {
            int kw = k16 * 8;
            uint32_t ah[4][4], am[4][4], bh[4][2], bm[4][2];
            #pragma unroll
            for (int i = 0; i < 4; i++) {
                int mrow = wy * 64 + i * 16 + r;
                const uint32_t* ph = base + AHI + mrow * 20 + kw + cq;
                ah[i][0] = ph[0]; ah[i][1] = ph[8 * 20]; ah[i][2] = ph[4]; ah[i][3] = ph[8 * 20 + 4];
                const uint32_t* pm = base + AMI + mrow * 20 + kw + cq;
                am[i][0] = pm[0]; am[i][1] = pm[8 * 20]; am[i][2] = pm[4]; am[i][3] = pm[8 * 20 + 4];
            }
            #pragma unroll
            for (int j = 0; j < 4; j++) {
                int nrow = wx * 32 + j * 8 + r;
                const uint32_t* ph = base + BHIo + nrow * 20 + kw + cq;
                bh[j][0] = ph[0]; bh[j][1] = ph[4];
                const uint32_t* pm = base + BMIo + nrow * 20 + kw + cq;
                bm[j][0] = pm[0]; bm[j][1] = pm[4];
            }
            #pragma unroll
            for (int i = 0; i < 4; i++)
                #pragma unroll
                for (int j = 0; j < 4; j++) {
                    mma16(acc[i][j], ah[i], bh[j]);
                    mma16(acc[i][j], am[i], bh[j]);
                    mma16(acc[i][j], ah[i], bm[j]);
                }
        }
    };

    loadG(0);
    storeS(0);
    __syncthreads();
    int NC = K >> 5;
    for (int c = 0; c < NC; c++) {
        if (c + 1 < NC) loadG(c + 1);
        compute(c & 1);
        if (c + 1 < NC) storeS((c + 1) & 1);
        __syncthreads();
    }

    int rowb = blockIdx.y * 128 + wy * 64;
    int colb = blockIdx.x * BN + wx * 32;
    #pragma unroll
    for (int i = 0; i < 4; i++) {
        #pragma unroll
        for (int j = 0; j < 4; j++) {
            int col = colb + j * 8 + cq * 2;
            #pragma unroll
            for (int h = 0; h < 2; h++) {
                int row = rowb + i * 16 + r + h * 8;
                float v0 = acc[i][j][h * 2], v1 = acc[i][j][h * 2 + 1];
                v0 += bias[col]; v1 += bias[col + 1];
                if (EPI == 1) {
                    float t0 = v0, t1 = v1;
                    v0 = 0.5f * t0 * (1.f + tanhf(0.7978845608028654f * (t0 + 0.044715f * t0 * t0 * t0)));
                    v1 = 0.5f * t1 * (1.f + tanhf(0.7978845608028654f * (t1 + 0.044715f * t1 * t1 * t1)));
                } else if (EPI == 2) {
                    float2 rv = *(const float2*)(args.res + (size_t)row * ldc + col);
                    v0 = rv.x + gate[col] * v0;
                    v1 = rv.y + gate[col + 1] * v1;
                }
                float2 ov; ov.x = v0; ov.y = v1;
                *(float2*)(C + (size_t)row * ldc + col) = ov;
            }
        }
    }
}

extern "C" void kernel_launch(void* const* d_in, const int* in_sizes, int n_in,
                              void* d_out, int out_size) {
    const float* video = (const float*)d_in[0];
    const float* action = (const float*)d_in[1];
    const float* vfreq = (const float*)d_in[2];
    const float* afreq = (const float*)d_in[3];
    const float* vtmod = (const float*)d_in[4];
    const float* atmod = (const float*)d_in[5];
    const float* Wq = (const float*)d_in[6];
    const float* Wk = (const float*)d_in[7];
    const float* Wv = (const float*)d_in[8];
    const float* Wo = (const float*)d_in[9];
    const float* bq = (const float*)d_in[10];
    const float* bk = (const float*)d_in[11];
    const float* bv = (const float*)d_in[12];
    const float* bo = (const float*)d_in[13];
    const float* gq = (const float*)d_in[14];
    const float* gk = (const float*)d_in[15];
    const float* mod = (const float*)d_in[16];
    const float* W1 = (const float*)d_in[17];
    const float* b1 = (const float*)d_in[18];
    const float* W2 = (const float*)d_in[19];
    const float* b2 = (const float*)d_in[20];
    float* out = (float*)d_out;

    float *x, *a, *q, *k, *v, *vt, *o, *hbuf, *m6;
    float *wqt, *wkt, *wvt, *wot, *w1t, *w2t;
    cudaGetSymbolAddress((void**)&x, g_x);
    cudaGetSymbolAddress((void**)&a, g_a);
    cudaGetSymbolAddress((void**)&q, g_q);
    cudaGetSymbolAddress((void**)&k, g_k);
    cudaGetSymbolAddress((void**)&v, g_v);
    cudaGetSymbolAddress((void**)&vt, g_vt);
    cudaGetSymbolAddress((void**)&o, g_o);
    cudaGetSymbolAddress((void**)&hbuf, g_h);
    cudaGetSymbolAddress((void**)&m6, g_m6);
    cudaGetSymbolAddress((void**)&wqt, g_wqt);
    cudaGetSymbolAddress((void**)&wkt, g_wkt);
    cudaGetSymbolAddress((void**)&wvt, g_wvt);
    cudaGetSymbolAddress((void**)&wot, g_wot);
    cudaGetSymbolAddress((void**)&w1t, g_w1t);
    cudaGetSymbolAddress((void**)&w2t, g_w2t);

    const int SM128 = (5120 + 128 * 40) * 2 * 4;
    cudaFuncSetAttribute(tgemm<128, 0>, cudaFuncAttributeMaxDynamicSharedMemorySize, SM128);
    cudaFuncSetAttribute(tgemm<128, 1>, cudaFuncAttributeMaxDynamicSharedMemorySize, SM128);
    cudaFuncSetAttribute(tgemm<128, 2>, cudaFuncAttributeMaxDynamicSharedMemorySize, SM128);

    dim3 tb(32, 8);
    // batched weight transposes (z = e*NL+l, 4 per weight)
    {
        dim3 gdd(D_MODEL / 32, D_MODEL / 32, 4);
        size_t msz = (size_t)D_MODEL * D_MODEL;
        transpose_kernel<<<gdd, tb>>>(Wq, wqt, D_MODEL, D_MODEL, msz);
        transpose_kernel<<<gdd, tb>>>(Wk, wkt, D_MODEL, D_MODEL, msz);
        transpose_kernel<<<gdd, tb>>>(Wv, wvt, D_MODEL, D_MODEL, msz);
        transpose_kernel<<<gdd, tb>>>(Wo, wot, D_MODEL, D_MODEL, msz);
        size_t msz1 = (size_t)D_MODEL * FF;
        transpose_kernel<<<dim3(FF / 32, D_MODEL / 32, 4), tb>>>(W1, w1t, D_MODEL, FF, msz1);
        transpose_kernel<<<dim3(D_MODEL / 32, FF / 32, 4), tb>>>(W2, w2t, FF, D_MODEL, msz1);
    }

    cudaMemcpyAsync(x, video, (size_t)SV * D_MODEL * 4, cudaMemcpyDeviceToDevice);
    cudaMemcpyAsync(x + (size_t)SV * D_MODEL, action, (size_t)SA * D_MODEL * 4, cudaMemcpyDeviceToDevice);

    for (int l = 0; l < NL; l++) {
        m6_kernel<<<48, 256>>>(mod, vtmod, atmod, m6, l);
        lnmod_kernel<<<S_TOT, 256>>>(x, a, m6, 0, 1);

        // QKV merged: grid (8, 20, 3)
        {
            GemmArgs ga = {};
            ga.A = a;
            ga.Bt[0] = wqt + (size_t)l * D_MODEL * D_MODEL;
            ga.Bt[1] = wkt + (size_t)l * D_MODEL * D_MODEL;
            ga.Bt[2] = wvt + (size_t)l * D_MODEL * D_MODEL;
            ga.bias[0] = bq + (size_t)l * D_MODEL;
            ga.bias[1] = bk + (size_t)l * D_MODEL;
            ga.bias[2] = bv + (size_t)l * D_MODEL;
            ga.C[0] = q; ga.C[1] = k; ga.C[2] = v;
            ga.K = D_MODEL; ga.lda = D_MODEL; ga.ldb = D_MODEL; ga.ldc = D_MODEL;
            ga.westride = (size_t)NL * D_MODEL * D_MODEL;
            ga.bestride = (size_t)NL * D_MODEL;
            tgemm<128, 0><<<dim3(D_MODEL / 128, S_TOT / 128, 3), 256, SM128>>>(ga);
        }
        rmsrope_kernel<<<2 * S_TOT, 256>>>(q, k, gq, gk, vfreq, afreq, l);

        transpose_kernel<<<dim3(D_MODEL / 32, S_TOT / 32, 1), tb>>>(v, vt, S_TOT, D_MODEL, 0);
        flash_kernel<<<dim3(NH, S_TOT / 64), 128>>>(q, k, vt, o);

        // O projection merged: grid (8, 20)
        {
            GemmArgs ga = {};
            ga.A = o;
            ga.Bt[0] = wot + (size_t)l * D_MODEL * D_MODEL;
            ga.bias[0] = bo + (size_t)l * D_MODEL;
            ga.C[0] = x;
            ga.res = x; ga.m6 = m6; ga.gidx = 2;
            ga.K = D_MODEL; ga.lda = D_MODEL; ga.ldb = D_MODEL; ga.ldc = D_MODEL;
            ga.westride = (size_t)NL * D_MODEL * D_MODEL;
            ga.bestride = (size_t)NL * D_MODEL;
            tgemm<128, 2><<<dim3(D_MODEL / 128, S_TOT / 128, 1), 256, SM128>>>(ga);
        }

        lnmod_kernel<<<S_TOT, 256>>>(x, a, m6, 3, 4);

        // MLP1 merged: grid (32, 20)
        {
            GemmArgs ga = {};
            ga.A = a;
            ga.Bt[0] = w1t + (size_t)l * D_MODEL * FF;
            ga.bias[0] = b1 + (size_t)l * FF;
            ga.C[0] = hbuf;
            ga.K = D_MODEL; ga.lda = D_MODEL; ga.ldb = D_MODEL; ga.ldc = FF;
            ga.westride = (size_t)NL * D_MODEL * FF;
            ga.bestride = (size_t)NL * FF;
            tgemm<128, 1><<<dim3(FF / 128, S_TOT / 128, 1), 256, SM128>>>(ga);
        }
        // MLP2 merged: grid (8, 20)
        {
            GemmArgs ga = {};
            ga.A = hbuf;
            ga.Bt[0] = w2t + (size_t)l * FF * D_MODEL;
            ga.bias[0] = b2 + (size_t)l * D_MODEL;
            ga.C[0] = x;
            ga.res = x; ga.m6 = m6; ga.gidx = 5;
            ga.K = FF; ga.lda = FF; ga.ldb = FF; ga.ldc = D_MODEL;
            ga.westride = (size_t)NL * FF * D_MODEL;
            ga.bestride = (size_t)NL * D_MODEL;
            tgemm<128, 2><<<dim3(D_MODEL / 128, S_TOT / 128, 1), 256, SM128>>>(ga);
        }
    }

    cudaMemcpyAsync(out, x, (size_t)S_TOT * D_MODEL * 4, cudaMemcpyDeviceToDevice);
}

// round 10
// speedup vs baseline: 5.0792x; 1.0812x over previous
#include <cuda_runtime.h>
#include <cuda_bf16.h>
#include <math.h>
#include <stdint.h>

#define SV 2048
#define SA 512
#define S_TOT 2560
#define D_MODEL 1024
#define NH 16
#define DH 64
#define FF 4096
#define NL 2
#define LOG2E 1.4426950408889634f

__device__ float g_x[S_TOT * D_MODEL];
__device__ float g_a[S_TOT * D_MODEL];
__device__ float g_q[S_TOT * D_MODEL];
__device__ float g_k[S_TOT * D_MODEL];
__device__ float g_v[S_TOT * D_MODEL];
__device__ float g_vt[D_MODEL * S_TOT];
__device__ float g_o[S_TOT * D_MODEL];
__device__ float g_h[S_TOT * FF];
__device__ float g_m6[2 * 6 * D_MODEL];
__device__ float g_wqt[NL * 2 * D_MODEL * D_MODEL];
__device__ float g_wkt[NL * 2 * D_MODEL * D_MODEL];
__device__ float g_wvt[NL * 2 * D_MODEL * D_MODEL];
__device__ float g_wot[NL * 2 * D_MODEL * D_MODEL];
__device__ float g_w1t[(size_t)NL * 2 * D_MODEL * FF];
__device__ float g_w2t[(size_t)NL * 2 * FF * D_MODEL];

struct GemmArgs {
    const float* A;
    const float* Bt[3];
    const float* bias[3];
    float* C[3];
    const float* res;
    const float* m6;
    int gidx;
    int K, lda, ldb, ldc;
    size_t westride, bestride;
};

__device__ __forceinline__ void mma16(float* d, const uint32_t* a, const uint32_t* b) {
    asm volatile("mma.sync.aligned.m16n8k16.row.col.f32.bf16.bf16.f32 "
        "{%0,%1,%2,%3}, {%4,%5,%6,%7}, {%8,%9}, {%0,%1,%2,%3};"
        : "+f"(d[0]), "+f"(d[1]), "+f"(d[2]), "+f"(d[3])
        : "r"(a[0]), "r"(a[1]), "r"(a[2]), "r"(a[3]), "r"(b[0]), "r"(b[1]));
}
__device__ __forceinline__ void ldsm_x4(uint32_t* r, uint32_t addr) {
    asm volatile("ldmatrix.sync.aligned.m8n8.x4.shared.b16 {%0,%1,%2,%3}, [%4];"
        : "=r"(r[0]), "=r"(r[1]), "=r"(r[2]), "=r"(r[3]) : "r"(addr));
}

// fast 2^x for x <= 0, FMA-pipe only
__device__ __forceinline__ float fexp2(float x) {
    x = fmaxf(x, -126.f);
    float fl = floorf(x);
    float f = x - fl;
    float p = 1.54035304e-4f;
    p = fmaf(p, f, 1.33335581e-3f);
    p = fmaf(p, f, 9.61812911e-3f);
    p = fmaf(p, f, 5.55041087e-2f);
    p = fmaf(p, f, 2.40226507e-1f);
    p = fmaf(p, f, 6.93147181e-1f);
    p = fmaf(p, f, 1.0f);
    return p * __int_as_float(((int)fl + 127) << 23);
}

__device__ __forceinline__ uint32_t pack_bf2(float a, float b) {
    __nv_bfloat162 t = __floats2bfloat162_rn(a, b);
    return *(const uint32_t*)&t;
}

__device__ __forceinline__ void blockReduce2(float& s, float& ss) {
    __shared__ float bufs[8], bufss[8];
    #pragma unroll
    for (int o = 16; o; o >>= 1) {
        s += __shfl_xor_sync(~0u, s, o); ss += __shfl_xor_sync(~0u, ss, o);
    }
    int w = threadIdx.x >> 5;
    if ((threadIdx.x & 31) == 0) { bufs[w] = s; bufss[w] = ss; }
    __syncthreads();
    if (threadIdx.x < 32) {
        s = (threadIdx.x < 8) ? bufs[threadIdx.x] : 0.f;
        ss = (threadIdx.x < 8) ? bufss[threadIdx.x] : 0.f;
        #pragma unroll
        for (int o = 4; o; o >>= 1) {
            s += __shfl_xor_sync(~0u, s, o); ss += __shfl_xor_sync(~0u, ss, o);
        }
        if (threadIdx.x == 0) { bufs[0] = s; bufss[0] = ss; }
    }
    __syncthreads();
    s = bufs[0]; ss = bufss[0];
}

__global__ void m6_kernel(const float* __restrict__ mod, const float* __restrict__ vt,
                          const float* __restrict__ at, float* __restrict__ m6, int l) {
    int idx = blockIdx.x * blockDim.x + threadIdx.x;
    if (idx >= 2 * 6 * D_MODEL) return;
    int e = idx / (6 * D_MODEL);
    int rem = idx % (6 * D_MODEL);
    m6[idx] = mod[((size_t)(e * NL + l) * 6) * D_MODEL + rem] + (e ? at[rem] : vt[rem]);
}

__global__ void __launch_bounds__(256) lnmod_kernel(const float* __restrict__ x, float* __restrict__ a,
                                                    const float* __restrict__ m6, int jsh, int jsc) {
    int row = blockIdx.x;
    int e = (row >= SV) ? 1 : 0;
    const float4* shv4 = (const float4*)(m6 + (size_t)(e * 6 + jsh) * D_MODEL);
    const float4* scv4 = (const float4*)(m6 + (size_t)(e * 6 + jsc) * D_MODEL);
    float4 v = ((const float4*)(x + (size_t)row * D_MODEL))[threadIdx.x];
    float s = v.x + v.y + v.z + v.w;
    float ss = v.x * v.x + v.y * v.y + v.z * v.z + v.w * v.w;
    blockReduce2(s, ss);
    float mu = s * (1.f / D_MODEL);
    float var = ss * (1.f / D_MODEL) - mu * mu;
    float r = rsqrtf(var + 1e-6f);
    float4 sh = shv4[threadIdx.x], sc = scv4[threadIdx.x];
    float4 o;
    o.x = (v.x - mu) * r * (1.f + sc.x) + sh.x;
    o.y = (v.y - mu) * r * (1.f + sc.y) + sh.y;
    o.z = (v.z - mu) * r * (1.f + sc.z) + sh.z;
    o.w = (v.w - mu) * r * (1.f + sc.w) + sh.w;
    ((float4*)(a + (size_t)row * D_MODEL))[threadIdx.x] = o;
}

// merged rmsnorm+rope for q and k
__global__ void __launch_bounds__(256) rmsrope_kernel(float* __restrict__ qb, float* __restrict__ kb,
                                                      const float* __restrict__ gq, const float* __restrict__ gk,
                                                      const float* __restrict__ vfreq, const float* __restrict__ afreq,
                                                      int l) {
    int bid = blockIdx.x;
    int isk = (bid >= S_TOT);
    int row = isk ? bid - S_TOT : bid;
    float* q = isk ? kb : qb;
    const float* gbase = isk ? gk : gq;
    int e = (row >= SV) ? 1 : 0;
    int pos = e ? row - SV : row;
    const float* fr = e ? (afreq + (size_t)pos * (DH / 2)) : (vfreq + (size_t)pos * (DH / 2));
    const float* g = gbase + (size_t)(e * NL + l) * D_MODEL;
    float4 v = ((const float4*)(q + (size_t)row * D_MODEL))[threadIdx.x];
    float ss = v.x * v.x + v.y * v.y + v.z * v.z + v.w * v.w, dummy = 0.f;
    blockReduce2(ss, dummy);
    float r = rsqrtf(ss * (1.f / D_MODEL) + 1e-6f);
    float4 gv = ((const float4*)g)[threadIdx.x];
    int d0 = threadIdx.x * 4;
    int j0 = (d0 & (DH - 1)) >> 1, j1 = j0 + 1;
    float c0 = cosf(fr[j0]), s0 = sinf(fr[j0]);
    float c1 = cosf(fr[j1]), s1 = sinf(fr[j1]);
    float xe0 = v.x * r * gv.x, xo0 = v.y * r * gv.y;
    float xe1 = v.z * r * gv.z, xo1 = v.w * r * gv.w;
    float4 o;
    o.x = xe0 * c0 - xo0 * s0; o.y = xe0 * s0 + xo0 * c0;
    o.z = xe1 * c1 - xo1 * s1; o.w = xe1 * s1 + xo1 * c1;
    ((float4*)(q + (size_t)row * D_MODEL))[threadIdx.x] = o;
}

// batched transpose
__global__ void __launch_bounds__(256) transpose_kernel(const float* __restrict__ src, float* __restrict__ dst,
                                                        int R, int C, size_t msize) {
    __shared__ float t[32][33];
    src += blockIdx.z * msize;
    dst += blockIdx.z * msize;
    int bx = blockIdx.x * 32, by = blockIdx.y * 32;
    for (int i = threadIdx.y; i < 32; i += 8)
        t[i][threadIdx.x] = src[(size_t)(by + i) * C + bx + threadIdx.x];
    __syncthreads();
    for (int i = threadIdx.y; i < 32; i += 8)
        dst[(size_t)(bx + i) * R + by + threadIdx.x] = t[threadIdx.x][i];
}

// ---------------- flash attention (bf16 3-term, online softmax, LDSM fragments) ----------------
#define FST 36
__global__ void __launch_bounds__(128) flash_kernel(
    const float* __restrict__ Q, const float* __restrict__ K,
    const float* __restrict__ Vt, float* __restrict__ O) {
    __shared__ __align__(16) uint32_t sQh[64 * FST], sQm[64 * FST], sKh[64 * FST], sKm[64 * FST],
                                      sVh[64 * FST], sVm[64 * FST];
    int h = blockIdx.x;
    int q0 = blockIdx.y * 64;
    int tid = threadIdx.x, wid = tid >> 5, lane = tid & 31;
    int r = lane >> 2, cq = lane & 3;

    uint32_t bQh = (uint32_t)__cvta_generic_to_shared(sQh);
    uint32_t bQm = (uint32_t)__cvta_generic_to_shared(sQm);
    uint32_t bKh = (uint32_t)__cvta_generic_to_shared(sKh);
    uint32_t bKm = (uint32_t)__cvta_generic_to_shared(sKm);
    uint32_t bVh = (uint32_t)__cvta_generic_to_shared(sVh);
    uint32_t bVm = (uint32_t)__cvta_generic_to_shared(sVm);
    uint32_t aoff = ((wid * 16 + (lane & 15)) * FST + ((lane >> 4) << 2)) * 4;
    uint32_t boff = ((((lane & 7) + ((lane >> 4) << 3)) * FST) + (((lane >> 3) & 1) << 2)) * 4;

    #pragma unroll
    for (int i = 0; i < 8; i++) {
        int idx = tid + i * 128;
        int row = idx >> 4, c4 = idx & 15;
        float4 f = *(const float4*)(Q + (size_t)(q0 + row) * D_MODEL + h * DH + c4 * 4);
        f.x *= 0.125f; f.y *= 0.125f; f.z *= 0.125f; f.w *= 0.125f;
        uint32_t h01 = pack_bf2(f.x, f.y), h23 = pack_bf2(f.z, f.w);
        __nv_bfloat162* H01 = (__nv_bfloat162*)&h01;
        __nv_bfloat162* H23 = (__nv_bfloat162*)&h23;
        uint32_t m01 = pack_bf2(f.x - __bfloat162float(H01->x), f.y - __bfloat162float(H01->y));
        uint32_t m23 = pack_bf2(f.z - __bfloat162float(H23->x), f.w - __bfloat162float(H23->y));
        int o2 = row * FST + c4 * 2;
        sQh[o2] = h01; sQh[o2 + 1] = h23;
        sQm[o2] = m01; sQm[o2 + 1] = m23;
    }

    int row0 = q0 + wid * 16 + r, row1 = row0 + 8;
    float mx0 = -1e30f, mx1 = -1e30f, l0 = 0.f, l1 = 0.f;
    float oa[8][4];
    #pragma unroll
    for (int j = 0; j < 8; j++)
        #pragma unroll
        for (int t = 0; t < 4; t++) oa[j][t] = 0.f;

    int kend = (q0 < SV) ? SV : (q0 + 64);
    for (int kb = 0; kb < kend; kb += 64) {
        __syncthreads();
        #pragma unroll
        for (int i = 0; i < 16; i++) {
            int idx = tid + i * 128;
            const float* src;
            uint32_t *dh_, *dm_;
            int row, c4;
            if (idx < 1024) {
                row = idx >> 4; c4 = idx & 15;
                src = K + (size_t)(kb + row) * D_MODEL + h * DH + c4 * 4;
                dh_ = sKh; dm_ = sKm;
            } else {
                int jj = idx - 1024;
                row = jj >> 4; c4 = jj & 15;
                src = Vt + (size_t)(h * DH + row) * S_TOT + kb + c4 * 4;
                dh_ = sVh; dm_ = sVm;
            }
            float4 f = *(const float4*)src;
            uint32_t h01 = pack_bf2(f.x, f.y), h23 = pack_bf2(f.z, f.w);
            __nv_bfloat162* H01 = (__nv_bfloat162*)&h01;
            __nv_bfloat162* H23 = (__nv_bfloat162*)&h23;
            uint32_t m01 = pack_bf2(f.x - __bfloat162float(H01->x), f.y - __bfloat162float(H01->y));
            uint32_t m23 = pack_bf2(f.z - __bfloat162float(H23->x), f.w - __bfloat162float(H23->y));
            int o2 = row * FST + c4 * 2;
            dh_[o2] = h01; dh_[o2 + 1] = h23;
            dm_[o2] = m01; dm_[o2 + 1] = m23;
        }
        __syncthreads();

        float s[8][4];
        #pragma unroll
        for (int j = 0; j < 8; j++)
            #pragma unroll
            for (int t = 0; t < 4; t++) s[j][t] = 0.f;
        #pragma unroll
        for (int k16 = 0; k16 < 4; k16++) {
            int kwB = k16 * 32;
            uint32_t ah[4], am[4];
            ldsm_x4(ah, bQh + aoff + kwB);
            ldsm_x4(am, bQm + aoff + kwB);
            #pragma unroll
            for (int jp = 0; jp < 8; jp += 2) {
                uint32_t bh4[4], bm4[4];
                ldsm_x4(bh4, bKh + boff + jp * 8 * FST * 4 + kwB);
                ldsm_x4(bm4, bKm + boff + jp * 8 * FST * 4 + kwB);
                mma16(s[jp], ah, bh4);
                mma16(s[jp], am, bh4);
                mma16(s[jp], ah, bm4);
                mma16(s[jp + 1], ah, bh4 + 2);
                mma16(s[jp + 1], am, bh4 + 2);
                mma16(s[jp + 1], ah, bm4 + 2);
            }
        }
        if (kb >= SV) {
            #pragma unroll
            for (int j = 0; j < 8; j++) {
                int key = kb + j * 8 + 2 * cq;
                if (key > row0) s[j][0] = -1e30f;
                if (key + 1 > row0) s[j][1] = -1e30f;
                if (key > row1) s[j][2] = -1e30f;
                if (key + 1 > row1) s[j][3] = -1e30f;
            }
        }
        float tm0 = -1e30f, tm1 = -1e30f;
        #pragma unroll
        for (int j = 0; j < 8; j++) {
            tm0 = fmaxf(tm0, fmaxf(s[j][0], s[j][1]));
            tm1 = fmaxf(tm1, fmaxf(s[j][2], s[j][3]));
        }
        tm0 = fmaxf(tm0, __shfl_xor_sync(~0u, tm0, 1));
        tm0 = fmaxf(tm0, __shfl_xor_sync(~0u, tm0, 2));
        tm1 = fmaxf(tm1, __shfl_xor_sync(~0u, tm1, 1));
        tm1 = fmaxf(tm1, __shfl_xor_sync(~0u, tm1, 2));
        float mn0 = fmaxf(mx0, tm0), mn1 = fmaxf(mx1, tm1);
        float corr0 = fexp2((mx0 - mn0) * LOG2E);
        float corr1 = fexp2((mx1 - mn1) * LOG2E);
        mx0 = mn0; mx1 = mn1;
        float ps0 = 0.f, ps1 = 0.f;
        #pragma unroll
        for (int j = 0; j < 8; j++) {
            s[j][0] = fexp2((s[j][0] - mn0) * LOG2E);
            s[j][1] = fexp2((s[j][1] - mn0) * LOG2E);
            s[j][2] = fexp2((s[j][2] - mn1) * LOG2E);
            s[j][3] = fexp2((s[j][3] - mn1) * LOG2E);
            ps0 += s[j][0] + s[j][1];
            ps1 += s[j][2] + s[j][3];
        }
        ps0 += __shfl_xor_sync(~0u, ps0, 1); ps0 += __shfl_xor_sync(~0u, ps0, 2);
        ps1 += __shfl_xor_sync(~0u, ps1, 1); ps1 += __shfl_xor_sync(~0u, ps1, 2);
        l0 = l0 * corr0 + ps0;
        l1 = l1 * corr1 + ps1;
        #pragma unroll
        for (int j = 0; j < 8; j++) {
            oa[j][0] *= corr0; oa[j][1] *= corr0;
            oa[j][2] *= corr1; oa[j][3] *= corr1;
        }
        #pragma unroll
        for (int j2 = 0; j2 < 4; j2++) {
            int t0 = 2 * j2, t1 = 2 * j2 + 1;
            uint32_t pah[4], pam[4];
            pah[0] = pack_bf2(s[t0][0], s[t0][1]);
            pah[1] = pack_bf2(s[t0][2], s[t0][3]);
            pah[2] = pack_bf2(s[t1][0], s[t1][1]);
            pah[3] = pack_bf2(s[t1][2], s[t1][3]);
            {
                __nv_bfloat162* B0 = (__nv_bfloat162*)&pah[0];
                __nv_bfloat162* B1 = (__nv_bfloat162*)&pah[1];
                __nv_bfloat162* B2 = (__nv_bfloat162*)&pah[2];
                __nv_bfloat162* B3 = (__nv_bfloat162*)&pah[3];
                pam[0] = pack_bf2(s[t0][0] - __bfloat162float(B0->x), s[t0][1] - __bfloat162float(B0->y));
                pam[1] = pack_bf2(s[t0][2] - __bfloat162float(B1->x), s[t0][3] - __bfloat162float(B1->y));
                pam[2] = pack_bf2(s[t1][0] - __bfloat162float(B2->x), s[t1][1] - __bfloat162float(B2->y));
                pam[3] = pack_bf2(s[t1][2] - __bfloat162float(B3->x), s[t1][3] - __bfloat162float(B3->y));
            }
            int kwB = j2 * 32;
            #pragma unroll
            for (int jp = 0; jp < 8; jp += 2) {
                uint32_t bh4[4], bm4[4];
                ldsm_x4(bh4, bVh + boff + jp * 8 * FST * 4 + kwB);
                ldsm_x4(bm4, bVm + boff + jp * 8 * FST * 4 + kwB);
                mma16(oa[jp], pah, bh4);
                mma16(oa[jp], pam, bh4);
                mma16(oa[jp], pah, bm4);
                mma16(oa[jp + 1], pah, bh4 + 2);
                mma16(oa[jp + 1], pam, bh4 + 2);
                mma16(oa[jp + 1], pah, bm4 + 2);
            }
        }
    }

    float inv0 = 1.f / l0, inv1 = 1.f / l1;
    #pragma unroll
    for (int jn = 0; jn < 8; jn++) {
        int col = h * DH + jn * 8 + cq * 2;
        float2 o0; o0.x = oa[jn][0] * inv0; o0.y = oa[jn][1] * inv0;
        float2 o1; o1.x = oa[jn][2] * inv1; o1.y = oa[jn][3] * inv1;
        *(float2*)(O + (size_t)row0 * D_MODEL + col) = o0;
        *(float2*)(O + (size_t)row1 * D_MODEL + col) = o1;
    }
}

// ---------- merged mma.sync 3-term BF16-split GEMM (LDSM fragments) ----------
template <int BN, int EPI>
__global__ void __launch_bounds__((BN == 128) ? 256 : 128) tgemm(GemmArgs args) {
    constexpr int THREADS = (BN == 128) ? 256 : 128;
    constexpr int NF4 = (128 + BN) * 8;
    constexpr int NPF = NF4 / THREADS;
    constexpr int AHI = 0, AMI = 2560, BHIo = 5120, BMIo = 5120 + BN * 20;
    constexpr int STG = 5120 + BN * 40;
    constexpr int WX = BN / 32;

    extern __shared__ uint32_t smw[];
    int tid = threadIdx.x;
    int wid = tid >> 5, lane = tid & 31;
    int wy = wid / WX, wx = wid % WX;
    int r = lane >> 2, cq = lane & 3;
    int z = blockIdx.z;
    int e = (blockIdx.y * 128 >= SV) ? 1 : 0;

    uint32_t sbase = (uint32_t)__cvta_generic_to_shared(smw);
    uint32_t aoff = ((wy * 64 + (lane & 15)) * 20 + ((lane >> 4) << 2)) * 4;
    // B lane offset INCLUDES the warp's n-tile base (wx*32 rows) — R9 bug fix
    uint32_t boff = ((wx * 32 + (lane & 7) + ((lane >> 4) << 3)) * 20 + (((lane >> 3) & 1) << 2)) * 4;

    int lda = args.lda, ldb = args.ldb, ldc = args.ldc;
    const float* A = args.A + (size_t)blockIdx.y * 128 * lda;
    const float* Bt = args.Bt[z] + (size_t)e * args.westride + (size_t)blockIdx.x * BN * ldb;
    const float* bias = args.bias[z] + (size_t)e * args.bestride;
    float* C = args.C[z];
    const float* gate = (EPI == 2) ? (args.m6 + (size_t)(e * 6 + args.gidx) * D_MODEL) : nullptr;
    int K = args.K;

    float acc[4][4][4];
    #pragma unroll
    for (int i = 0; i < 4; i++)
        #pragma unroll
        for (int j = 0; j < 4; j++)
            #pragma unroll
            for (int t = 0; t < 4; t++) acc[i][j][t] = 0.f;

    float4 pf[NPF];

    auto loadG = [&](int c) {
        #pragma unroll
        for (int t = 0; t < NPF; t++) {
            int idx = tid + t * THREADS;
            const float* src;
            if (idx < 1024) src = A + (size_t)(idx >> 3) * lda + c * 32 + (idx & 7) * 4;
            else { int bi = idx - 1024; src = Bt + (size_t)(bi >> 3) * ldb + c * 32 + (bi & 7) * 4; }
            pf[t] = *(const float4*)src;
        }
    };
    auto storeS = [&](int s) {
        uint32_t* base = smw + s * STG;
        #pragma unroll
        for (int t = 0; t < NPF; t++) {
            float4 f = pf[t];
            uint32_t h01 = pack_bf2(f.x, f.y), h23 = pack_bf2(f.z, f.w);
            __nv_bfloat162* H01 = (__nv_bfloat162*)&h01;
            __nv_bfloat162* H23 = (__nv_bfloat162*)&h23;
            uint32_t m01 = pack_bf2(f.x - __bfloat162float(H01->x), f.y - __bfloat162float(H01->y));
            uint32_t m23 = pack_bf2(f.z - __bfloat162float(H23->x), f.w - __bfloat162float(H23->y));
            int idx = tid + t * THREADS;
            uint32_t* dst;
            int mo;
            if (idx < 1024) { dst = base + AHI + (idx >> 3) * 20 + (idx & 7) * 2; mo = AMI - AHI; }
            else { int bi = idx - 1024; dst = base + BHIo + (bi >> 3) * 20 + (bi & 7) * 2; mo = BMIo - BHIo; }
            dst[0] = h01; dst[1] = h23;
            dst[mo] = m01; dst[mo + 1] = m23;
        }
    };
    auto compute = [&](int s) {
        uint32_t stb = sbase + s * STG * 4;
        #pragma unroll
        for (int k16 = 0; k16 < 2; k16++) {
            int kwB = k16 * 32;
            uint32_t ah[4][4], am[4][4], bh[2][4], bm[2][4];
            #pragma unroll
            for (int i = 0; i < 4; i++) {
                ldsm_x4(ah[i], stb + aoff + i * 16 * 20 * 4 + kwB);
                ldsm_x4(am[i], stb + AMI * 4 + aoff + i * 16 * 20 * 4 + kwB);
            }
            #pragma unroll
            for (int jp = 0; jp < 2; jp++) {
                ldsm_x4(bh[jp], stb + BHIo * 4 + boff + jp * 16 * 20 * 4 + kwB);
                ldsm_x4(bm[jp], stb + BMIo * 4 + boff + jp * 16 * 20 * 4 + kwB);
            }
            #pragma unroll
            for (int i = 0; i < 4; i++)
                #pragma unroll
                for (int j = 0; j < 4; j++) {
                    const uint32_t* bhj = bh[j >> 1] + (j & 1) * 2;
                    const uint32_t* bmj = bm[j >> 1] + (j & 1) * 2;
                    mma16(acc[i][j], ah[i], bhj);
                    mma16(acc[i][j], am[i], bhj);
                    mma16(acc[i][j], ah[i], bmj);
                }
        }
    };

    loadG(0);
    storeS(0);
    __syncthreads();
    int NC = K >> 5;
    for (int c = 0; c < NC; c++) {
        if (c + 1 < NC) loadG(c + 1);
        compute(c & 1);
        if (c + 1 < NC) storeS((c + 1) & 1);
        __syncthreads();
    }

    int rowb = blockIdx.y * 128 + wy * 64;
    int colb = blockIdx.x * BN + wx * 32;
    #pragma unroll
    for (int i = 0; i < 4; i++) {
        #pragma unroll
        for (int j = 0; j < 4; j++) {
            int col = colb + j * 8 + cq * 2;
            #pragma unroll
            for (int h = 0; h < 2; h++) {
                int row = rowb + i * 16 + r + h * 8;
                float v0 = acc[i][j][h * 2], v1 = acc[i][j][h * 2 + 1];
                v0 += bias[col]; v1 += bias[col + 1];
                if (EPI == 1) {
                    float t0 = v0, t1 = v1;
                    v0 = 0.5f * t0 * (1.f + tanhf(0.7978845608028654f * (t0 + 0.044715f * t0 * t0 * t0)));
                    v1 = 0.5f * t1 * (1.f + tanhf(0.7978845608028654f * (t1 + 0.044715f * t1 * t1 * t1)));
                } else if (EPI == 2) {
                    float2 rv = *(const float2*)(args.res + (size_t)row * ldc + col);
                    v0 = rv.x + gate[col] * v0;
                    v1 = rv.y + gate[col + 1] * v1;
                }
                float2 ov; ov.x = v0; ov.y = v1;
                *(float2*)(C + (size_t)row * ldc + col) = ov;
            }
        }
    }
}

extern "C" void kernel_launch(void* const* d_in, const int* in_sizes, int n_in,
                              void* d_out, int out_size) {
    const float* video = (const float*)d_in[0];
    const float* action = (const float*)d_in[1];
    const float* vfreq = (const float*)d_in[2];
    const float* afreq = (const float*)d_in[3];
    const float* vtmod = (const float*)d_in[4];
    const float* atmod = (const float*)d_in[5];
    const float* Wq = (const float*)d_in[6];
    const float* Wk = (const float*)d_in[7];
    const float* Wv = (const float*)d_in[8];
    const float* Wo = (const float*)d_in[9];
    const float* bq = (const float*)d_in[10];
    const float* bk = (const float*)d_in[11];
    const float* bv = (const float*)d_in[12];
    const float* bo = (const float*)d_in[13];
    const float* gq = (const float*)d_in[14];
    const float* gk = (const float*)d_in[15];
    const float* mod = (const float*)d_in[16];
    const float* W1 = (const float*)d_in[17];
    const float* b1 = (const float*)d_in[18];
    const float* W2 = (const float*)d_in[19];
    const float* b2 = (const float*)d_in[20];
    float* out = (float*)d_out;

    float *x, *a, *q, *k, *v, *vt, *o, *hbuf, *m6;
    float *wqt, *wkt, *wvt, *wot, *w1t, *w2t;
    cudaGetSymbolAddress((void**)&x, g_x);
    cudaGetSymbolAddress((void**)&a, g_a);
    cudaGetSymbolAddress((void**)&q, g_q);
    cudaGetSymbolAddress((void**)&k, g_k);
    cudaGetSymbolAddress((void**)&v, g_v);
    cudaGetSymbolAddress((void**)&vt, g_vt);
    cudaGetSymbolAddress((void**)&o, g_o);
    cudaGetSymbolAddress((void**)&hbuf, g_h);
    cudaGetSymbolAddress((void**)&m6, g_m6);
    cudaGetSymbolAddress((void**)&wqt, g_wqt);
    cudaGetSymbolAddress((void**)&wkt, g_wkt);
    cudaGetSymbolAddress((void**)&wvt, g_wvt);
    cudaGetSymbolAddress((void**)&wot, g_wot);
    cudaGetSymbolAddress((void**)&w1t, g_w1t);
    cudaGetSymbolAddress((void**)&w2t, g_w2t);

    const int SM128 = (5120 + 128 * 40) * 2 * 4;
    cudaFuncSetAttribute(tgemm<128, 0>, cudaFuncAttributeMaxDynamicSharedMemorySize, SM128);
    cudaFuncSetAttribute(tgemm<128, 1>, cudaFuncAttributeMaxDynamicSharedMemorySize, SM128);
    cudaFuncSetAttribute(tgemm<128, 2>, cudaFuncAttributeMaxDynamicSharedMemorySize, SM128);

    dim3 tb(32, 8);
    {
        dim3 gdd(D_MODEL / 32, D_MODEL / 32, 4);
        size_t msz = (size_t)D_MODEL * D_MODEL;
        transpose_kernel<<<gdd, tb>>>(Wq, wqt, D_MODEL, D_MODEL, msz);
        transpose_kernel<<<gdd, tb>>>(Wk, wkt, D_MODEL, D_MODEL, msz);
        transpose_kernel<<<gdd, tb>>>(Wv, wvt, D_MODEL, D_MODEL, msz);
        transpose_kernel<<<gdd, tb>>>(Wo, wot, D_MODEL, D_MODEL, msz);
        size_t msz1 = (size_t)D_MODEL * FF;
        transpose_kernel<<<dim3(FF / 32, D_MODEL / 32, 4), tb>>>(W1, w1t, D_MODEL, FF, msz1);
        transpose_kernel<<<dim3(D_MODEL / 32, FF / 32, 4), tb>>>(W2, w2t, FF, D_MODEL, msz1);
    }

    cudaMemcpyAsync(x, video, (size_t)SV * D_MODEL * 4, cudaMemcpyDeviceToDevice);
    cudaMemcpyAsync(x + (size_t)SV * D_MODEL, action, (size_t)SA * D_MODEL * 4, cudaMemcpyDeviceToDevice);

    for (int l = 0; l < NL; l++) {
        m6_kernel<<<48, 256>>>(mod, vtmod, atmod, m6, l);
        lnmod_kernel<<<S_TOT, 256>>>(x, a, m6, 0, 1);

        {
            GemmArgs ga = {};
            ga.A = a;
            ga.Bt[0] = wqt + (size_t)l * D_MODEL * D_MODEL;
            ga.Bt[1] = wkt + (size_t)l * D_MODEL * D_MODEL;
            ga.Bt[2] = wvt + (size_t)l * D_MODEL * D_MODEL;
            ga.bias[0] = bq + (size_t)l * D_MODEL;
            ga.bias[1] = bk + (size_t)l * D_MODEL;
            ga.bias[2] = bv + (size_t)l * D_MODEL;
            ga.C[0] = q; ga.C[1] = k; ga.C[2] = v;
            ga.K = D_MODEL; ga.lda = D_MODEL; ga.ldb = D_MODEL; ga.ldc = D_MODEL;
            ga.westride = (size_t)NL * D_MODEL * D_MODEL;
            ga.bestride = (size_t)NL * D_MODEL;
            tgemm<128, 0><<<dim3(D_MODEL / 128, S_TOT / 128, 3), 256, SM128>>>(ga);
        }
        rmsrope_kernel<<<2 * S_TOT, 256>>>(q, k, gq, gk, vfreq, afreq, l);

        transpose_kernel<<<dim3(D_MODEL / 32, S_TOT / 32, 1), tb>>>(v, vt, S_TOT, D_MODEL, 0);
        flash_kernel<<<dim3(NH, S_TOT / 64), 128>>>(q, k, vt, o);

        {
            GemmArgs ga = {};
            ga.A = o;
            ga.Bt[0] = wot + (size_t)l * D_MODEL * D_MODEL;
            ga.bias[0] = bo + (size_t)l * D_MODEL;
            ga.C[0] = x;
            ga.res = x; ga.m6 = m6; ga.gidx = 2;
            ga.K = D_MODEL; ga.lda = D_MODEL; ga.ldb = D_MODEL; ga.ldc = D_MODEL;
            ga.westride = (size_t)NL * D_MODEL * D_MODEL;
            ga.bestride = (size_t)NL * D_MODEL;
            tgemm<128, 2><<<dim3(D_MODEL / 128, S_TOT / 128, 1), 256, SM128>>>(ga);
        }

        lnmod_kernel<<<S_TOT, 256>>>(x, a, m6, 3, 4);

        {
            GemmArgs ga = {};
            ga.A = a;
            ga.Bt[0] = w1t + (size_t)l * D_MODEL * FF;
            ga.bias[0] = b1 + (size_t)l * FF;
            ga.C[0] = hbuf;
            ga.K = D_MODEL; ga.lda = D_MODEL; ga.ldb = D_MODEL; ga.ldc = FF;
            ga.westride = (size_t)NL * D_MODEL * FF;
            ga.bestride = (size_t)NL * FF;
            tgemm<128, 1><<<dim3(FF / 128, S_TOT / 128, 1), 256, SM128>>>(ga);
        }
        {
            GemmArgs ga = {};
            ga.A = hbuf;
            ga.Bt[0] = w2t + (size_t)l * FF * D_MODEL;
            ga.bias[0] = b2 + (size_t)l * D_MODEL;
            ga.C[0] = x;
            ga.res = x; ga.m6 = m6; ga.gidx = 5;
            ga.K = FF; ga.lda = FF; ga.ldb = FF; ga.ldc = D_MODEL;
            ga.westride = (size_t)NL * FF * D_MODEL;
            ga.bestride = (size_t)NL * D_MODEL;
            tgemm<128, 2><<<dim3(D_MODEL / 128, S_TOT / 128, 1), 256, SM128>>>(ga);
        }
    }

    cudaMemcpyAsync(out, x, (size_t)S_TOT * D_MODEL * 4, cudaMemcpyDeviceToDevice);
}